// round 3
// baseline (speedup 1.0000x reference)
#include <cuda_runtime.h>
#include <math.h>
#include <stdint.h>

// Problem constants (fixed shapes)
//  B=4, N=4096, D=1024, H=16, M=256, dk=64
#define BB   4
#define NN   4096
#define DD   1024
#define HH   16
#define MM   256
#define DKK  64
#define BN   (BB*NN)          // 16384
#define BH   (BB*HH)          // 64
#define D3   (3*DD)           // 3072

// 1/sqrt(256 + 1e-6) rounds to exactly 0.0625 in fp32
#define INV_SQRT_M 0.0625f
#define EPS_DENOM  1e-6f

// ---------------- device scratch (no allocations allowed) -----------------
__device__ float g_qkv[(size_t)BN * D3];              // 201 MB
__device__ float g_Qf [(size_t)BH * NN * MM];         // 67 MB
__device__ float g_Kf [(size_t)BH * NN * MM];         // 67 MB (reused as ctx)
__device__ float g_Spart[(size_t)8 * BH * MM * DKK];  // 32 MB
__device__ float g_Kpart[(size_t)8 * BH * MM];        // 512 KB
__device__ float g_S  [(size_t)BH * MM * DKK];        // 4 MB
__device__ float g_Ksum[(size_t)BH * MM];             // 64 KB
__device__ float g_valid[(size_t)BN];                 // canonical validity (1=keep)
__device__ int   g_mask_mode;                         // 0=int32, 1=float32, 2=uint8

// ===========================================================================
// Mask dtype detection + expansion to canonical float validity array.
// Scans the first 4096 u32 words (16 KB) — in-bounds for every candidate
// encoding of the 16384-element mask. Encodings are mutually exclusive:
//   int32:   words in {0,1}
//   float32: words in {0, 0x3F800000}
//   uint8:   packed bytes in {0,1} -> words like 0x100/0x10000/0x01000100
// ===========================================================================
__global__ void mask_detect_kernel(const unsigned int* __restrict__ mw)
{
    __shared__ int sawF, sawB;
    if (threadIdx.x == 0) { sawF = 0; sawB = 0; }
    __syncthreads();
    for (int i = threadIdx.x; i < 4096; i += 256) {
        unsigned int v = mw[i];
        if (v == 0x3F800000u) atomicOr(&sawF, 1);
        else if (v != 0u && v != 1u) atomicOr(&sawB, 1);
    }
    __syncthreads();
    if (threadIdx.x == 0) g_mask_mode = sawF ? 1 : (sawB ? 2 : 0);
}

__global__ void mask_expand_kernel(const void* __restrict__ m, float* __restrict__ valid)
{
    int i = blockIdx.x * 256 + threadIdx.x;
    if (i >= BN) return;
    int mode = g_mask_mode;
    bool pad;
    if (mode == 0)      pad = ((const int*)m)[i] != 0;
    else if (mode == 1) pad = ((const float*)m)[i] != 0.0f;
    else                pad = ((const unsigned char*)m)[i] != 0;
    valid[i] = pad ? 0.0f : 1.0f;
}

// ===========================================================================
// Generic C = A(MxK,row) * Bt(NxK,row)^T + bias(N).  128x128 tile, BK=16,
// 256 threads, 8x8 micro-tile with strided (conflict-free) smem reads.
// ===========================================================================
__global__ __launch_bounds__(256) void gemm_nt_bias(
    const float* __restrict__ A, const float* __restrict__ Bt,
    const float* __restrict__ bias, float* __restrict__ C,
    int Md, int Nd, int Kd)
{
    __shared__ float As[16][132];
    __shared__ float Bs[16][132];

    const int tid = threadIdx.x;
    const int ty = tid >> 4;          // 0..15
    const int tx = tid & 15;          // 0..15
    const int rowBase = blockIdx.y * 128;
    const int colBase = blockIdx.x * 128;

    const float* Ap = A  + (size_t)rowBase * Kd;
    const float* Bp = Bt + (size_t)colBase * Kd;

    float acc[8][8];
#pragma unroll
    for (int i = 0; i < 8; i++)
#pragma unroll
        for (int j = 0; j < 8; j++) acc[i][j] = 0.f;

    for (int k0 = 0; k0 < Kd; k0 += 16) {
#pragma unroll
        for (int t = 0; t < 2; t++) {
            int v  = tid + t * 256;         // 0..511 float4 slots
            int r  = v >> 2;                // 0..127
            int c4 = (v & 3) * 4;           // 0,4,8,12
            float4 fa = *reinterpret_cast<const float4*>(Ap + (size_t)r * Kd + k0 + c4);
            As[c4 + 0][r] = fa.x; As[c4 + 1][r] = fa.y;
            As[c4 + 2][r] = fa.z; As[c4 + 3][r] = fa.w;
            float4 fb = *reinterpret_cast<const float4*>(Bp + (size_t)r * Kd + k0 + c4);
            Bs[c4 + 0][r] = fb.x; Bs[c4 + 1][r] = fb.y;
            Bs[c4 + 2][r] = fb.z; Bs[c4 + 3][r] = fb.w;
        }
        __syncthreads();
#pragma unroll
        for (int k = 0; k < 16; k++) {
            float a[8], b[8];
#pragma unroll
            for (int i = 0; i < 8; i++) a[i] = As[k][ty + i * 16];
#pragma unroll
            for (int j = 0; j < 8; j++) b[j] = Bs[k][tx + j * 16];
#pragma unroll
            for (int i = 0; i < 8; i++)
#pragma unroll
                for (int j = 0; j < 8; j++) acc[i][j] += a[i] * b[j];
        }
        __syncthreads();
    }

#pragma unroll
    for (int i = 0; i < 8; i++) {
        int r = rowBase + ty + i * 16;
#pragma unroll
        for (int j = 0; j < 8; j++) {
            int c = colBase + tx + j * 16;
            C[(size_t)r * Nd + c] = acc[i][j] + bias[c];
        }
    }
}

// ===========================================================================
// phi kernel: for a 64-row tile of one (b,h), compute
//   proj = T @ omega[h]^T  (64x64 @ 64x256), rowmax, sq = 0.5*|t|^2,
//   out  = exp(proj - rowmax - sq) * 0.0625 [* valid for K]
// grid: (N/64, B*H, 2[z=0:Q, z=1:K]); 256 threads (16x16).
// ===========================================================================
__global__ __launch_bounds__(256) void phi_kernel(
    const float* __restrict__ qkv, const float* __restrict__ omega,
    const float* __restrict__ valid,
    float* __restrict__ Qf, float* __restrict__ Kf)
{
    const int ntile = blockIdx.x;
    const int bh    = blockIdx.y;
    const int isK   = blockIdx.z;
    const int b = bh >> 4, h = bh & 15;
    const int n0 = ntile * 64;
    const int tid = threadIdx.x;
    const int ty = tid >> 4, tx = tid & 15;

    __shared__ float Ts[16][68];      // [k][row]
    __shared__ float Om[16][257];     // [k][m]
    __shared__ float validS[64];

    if (tid < 64)
        validS[tid] = valid[b * NN + n0 + tid];

    const float* src = qkv + ((size_t)(b * NN + n0)) * D3 + (size_t)isK * DD + h * DKK;
    const float* om  = omega + (size_t)h * MM * DKK;

    float acc[4][16];
    float sq[4];
#pragma unroll
    for (int i = 0; i < 4; i++) {
        sq[i] = 0.f;
#pragma unroll
        for (int j = 0; j < 16; j++) acc[i][j] = 0.f;
    }

    for (int kc = 0; kc < 4; kc++) {
        __syncthreads();                         // also orders validS before use
        for (int i = tid; i < 64 * 16; i += 256) {
            int r = i >> 4, kk = i & 15;
            float v = src[(size_t)r * D3 + kc * 16 + kk];
            if (!isK) v *= validS[r];            // Q is masked BEFORE phi
            Ts[kk][r] = v;
        }
        for (int i = tid; i < 256 * 16; i += 256) {
            int m = i >> 4, kk = i & 15;
            Om[kk][m] = om[(size_t)m * DKK + kc * 16 + kk];
        }
        __syncthreads();
#pragma unroll
        for (int k = 0; k < 16; k++) {
            float a[4];
#pragma unroll
            for (int i = 0; i < 4; i++) {
                a[i] = Ts[k][ty + i * 16];
                sq[i] += a[i] * a[i];
            }
#pragma unroll
            for (int j = 0; j < 16; j++) {
                float bx = Om[k][tx + j * 16];
#pragma unroll
                for (int i = 0; i < 4; i++) acc[i][j] += a[i] * bx;
            }
        }
    }

    float base[4];
#pragma unroll
    for (int i = 0; i < 4; i++) {
        float mx = acc[i][0];
#pragma unroll
        for (int j = 1; j < 16; j++) mx = fmaxf(mx, acc[i][j]);
#pragma unroll
        for (int s = 1; s < 16; s <<= 1)
            mx = fmaxf(mx, __shfl_xor_sync(0xffffffffu, mx, s));
        base[i] = -mx - 0.5f * sq[i];
    }

    float* dst = (isK ? Kf : Qf) + ((size_t)bh * NN + n0) * MM;
#pragma unroll
    for (int i = 0; i < 4; i++) {
        int r = ty + i * 16;
        float post = isK ? (INV_SQRT_M * validS[r]) : INV_SQRT_M;
#pragma unroll
        for (int j = 0; j < 16; j++) {
            dst[(size_t)r * MM + tx + j * 16] = expf(acc[i][j] + base[i]) * post;
        }
    }
}

// ===========================================================================
// S kernel (split-K, deterministic): for (b,h) and an n-chunk of 512,
//   Spart[m,d] = sum_n Kf[n,m] * V[n,d],  Kpart[m] = sum_n Kf[n,m]
// (No V masking needed: Kf is exactly 0 at padded rows.)
// ===========================================================================
__global__ __launch_bounds__(256) void s_kernel(
    const float* __restrict__ Kf, const float* __restrict__ qkv,
    float* __restrict__ Spart, float* __restrict__ Kpart)
{
    const int chunk = blockIdx.x;     // 0..7
    const int bh    = blockIdx.y;     // 0..63
    const int b = bh >> 4, h = bh & 15;
    const int n0 = chunk * 512;
    const int tid = threadIdx.x;
    const int mg = tid >> 3;          // 0..31
    const int dg = tid & 7;           // 0..7

    __shared__ float Ks[16][256];
    __shared__ float Vs[16][64];

    float acc[8][8];
    float ks[8];
#pragma unroll
    for (int i = 0; i < 8; i++) {
        ks[i] = 0.f;
#pragma unroll
        for (int j = 0; j < 8; j++) acc[i][j] = 0.f;
    }

    const float* kf   = Kf + ((size_t)bh * NN + n0) * MM;
    const float* vsrc = qkv + ((size_t)(b * NN + n0)) * D3 + 2 * DD + h * DKK;

    for (int sub = 0; sub < 32; sub++) {
        __syncthreads();
        for (int i = tid; i < 16 * 256; i += 256) {
            int n = i >> 8, m = i & 255;
            Ks[n][m] = kf[(size_t)(sub * 16 + n) * MM + m];
        }
        for (int i = tid; i < 16 * 64; i += 256) {
            int n = i >> 6, d = i & 63;
            Vs[n][d] = vsrc[(size_t)(sub * 16 + n) * D3 + d];
        }
        __syncthreads();
#pragma unroll
        for (int n = 0; n < 16; n++) {
            float a[8], bx[8];
#pragma unroll
            for (int i = 0; i < 8; i++) a[i] = Ks[n][mg + i * 32];
#pragma unroll
            for (int j = 0; j < 8; j++) bx[j] = Vs[n][dg + j * 8];
#pragma unroll
            for (int i = 0; i < 8; i++) {
                ks[i] += a[i];
#pragma unroll
                for (int j = 0; j < 8; j++) acc[i][j] += a[i] * bx[j];
            }
        }
    }

    float* Sp = Spart + ((size_t)chunk * BH + bh) * (MM * DKK);
    float* Kp = Kpart + ((size_t)chunk * BH + bh) * MM;
#pragma unroll
    for (int i = 0; i < 8; i++) {
        int m = mg + i * 32;
#pragma unroll
        for (int j = 0; j < 8; j++)
            Sp[m * DKK + dg + j * 8] = acc[i][j];
        if (dg == 0) Kp[m] = ks[i];
    }
}

// Deterministic reduce of the 8 split-K partials.
__global__ __launch_bounds__(256) void reduce_kernel(
    const float* __restrict__ Spart, const float* __restrict__ Kpart,
    float* __restrict__ S, float* __restrict__ Ksum)
{
    int i = blockIdx.x * 256 + threadIdx.x;
    const size_t SSZ = (size_t)BH * MM * DKK;      // 1,048,576
    const size_t KSZ = (size_t)BH * MM;            // 16,384
    if (i < (int)SSZ) {
        float s = 0.f;
#pragma unroll
        for (int c = 0; c < 8; c++) s += Spart[(size_t)c * SSZ + i];
        S[i] = s;
    }
    if (i < (int)KSZ) {
        float s = 0.f;
#pragma unroll
        for (int c = 0; c < 8; c++) s += Kpart[(size_t)c * KSZ + i];
        Ksum[i] = s;
    }
}

// ===========================================================================
// ctx kernel: per (b,h), 64-row tile:
//   num = Qf(64x256) @ S(256x64); den = Qf . Ksum; ctx = num/(den+eps)*valid
// ===========================================================================
__global__ __launch_bounds__(256) void ctx_kernel(
    const float* __restrict__ Qf, const float* __restrict__ S,
    const float* __restrict__ Ksum, const float* __restrict__ valid,
    float* __restrict__ ctx)
{
    const int ntile = blockIdx.x;
    const int bh    = blockIdx.y;
    const int b = bh >> 4, h = bh & 15;
    const int n0 = ntile * 64;
    const int tid = threadIdx.x;
    const int ty = tid >> 4, tx = tid & 15;

    __shared__ float Qs[64][65];
    __shared__ float Ss[64][65];
    __shared__ float Ksm[256];
    __shared__ float validS[64];

    if (tid < 64) validS[tid] = valid[b * NN + n0 + tid];
    Ksm[tid] = Ksum[bh * MM + tid];

    float acc[4][4];
    float den[4];
#pragma unroll
    for (int i = 0; i < 4; i++) {
        den[i] = 0.f;
#pragma unroll
        for (int j = 0; j < 4; j++) acc[i][j] = 0.f;
    }

    const float* qf = Qf + ((size_t)bh * NN + n0) * MM;
    const float* Sp = S + (size_t)bh * MM * DKK;

    for (int mc = 0; mc < 4; mc++) {
        __syncthreads();
        for (int i = tid; i < 64 * 64; i += 256) {
            int r = i >> 6, m = i & 63;
            Qs[r][m] = qf[(size_t)r * MM + mc * 64 + m];
        }
        for (int i = tid; i < 64 * 64; i += 256) {
            int m = i >> 6, d = i & 63;
            Ss[m][d] = Sp[(mc * 64 + m) * DKK + d];
        }
        __syncthreads();
#pragma unroll 8
        for (int m = 0; m < 64; m++) {
            float kv = Ksm[mc * 64 + m];
            float a[4], bx[4];
#pragma unroll
            for (int i = 0; i < 4; i++) a[i] = Qs[ty + i * 16][m];
#pragma unroll
            for (int j = 0; j < 4; j++) bx[j] = Ss[m][tx + j * 16];
#pragma unroll
            for (int i = 0; i < 4; i++) {
                den[i] += a[i] * kv;
#pragma unroll
                for (int j = 0; j < 4; j++) acc[i][j] += a[i] * bx[j];
            }
        }
    }

#pragma unroll
    for (int i = 0; i < 4; i++) {
        int r = ty + i * 16;
        float scale = validS[r] / (den[i] + EPS_DENOM);
        float* dst = ctx + ((size_t)(b * NN) + n0 + r) * DD + h * DKK;
#pragma unroll
        for (int j = 0; j < 4; j++)
            dst[tx + j * 16] = acc[i][j] * scale;
    }
}

// ===========================================================================
extern "C" void kernel_launch(void* const* d_in, const int* in_sizes, int n_in,
                              void* d_out, int out_size)
{
    const float* x     = (const float*)d_in[0];
    const float* Wqkv  = (const float*)d_in[1];
    const float* bqkv  = (const float*)d_in[2];
    const float* Wout  = (const float*)d_in[3];
    const float* bout  = (const float*)d_in[4];
    const float* omega = (const float*)d_in[5];
    const void*  maskp = d_in[6];               // dtype detected at runtime
    float* out = (float*)d_out;

    float *qkv, *Qf, *Kf, *Spart, *Kpart, *S, *Ksum, *valid;
    cudaGetSymbolAddress((void**)&qkv,   g_qkv);
    cudaGetSymbolAddress((void**)&Qf,    g_Qf);
    cudaGetSymbolAddress((void**)&Kf,    g_Kf);
    cudaGetSymbolAddress((void**)&Spart, g_Spart);
    cudaGetSymbolAddress((void**)&Kpart, g_Kpart);
    cudaGetSymbolAddress((void**)&S,     g_S);
    cudaGetSymbolAddress((void**)&Ksum,  g_Ksum);
    cudaGetSymbolAddress((void**)&valid, g_valid);
    float* ctx = Kf;   // alias: Kf dead after s_kernel; ctx written after reduce

    // 0) canonicalize the padding mask (dtype-robust)
    mask_detect_kernel<<<1, 256>>>((const unsigned int*)maskp);
    mask_expand_kernel<<<BN / 256, 256>>>(maskp, valid);

    // 1) qkv = x @ Wqkv^T + bqkv          (16384 x 3072, K=1024)
    gemm_nt_bias<<<dim3(D3 / 128, BN / 128), 256>>>(x, Wqkv, bqkv, qkv, BN, D3, DD);

    // 2) phi for Q and K                   (grid.z: 0=Q, 1=K)
    phi_kernel<<<dim3(NN / 64, BH, 2), 256>>>(qkv, omega, valid, Qf, Kf);

    // 3) S = Kf^T V, Ksum = Kf^T 1  (split-K partials, deterministic reduce)
    s_kernel<<<dim3(8, BH), 256>>>(Kf, qkv, Spart, Kpart);
    reduce_kernel<<<4096, 256>>>(Spart, Kpart, S, Ksum);

    // 4) ctx = (Qf @ S) / (Qf . Ksum + eps) * valid, written as (B,N,D)
    ctx_kernel<<<dim3(NN / 64, BH), 256>>>(Qf, S, Ksum, valid, ctx);

    // 5) out = ctx @ Wout^T + bout         (16384 x 1024, K=1024)
    gemm_nt_bias<<<dim3(DD / 128, BN / 128), 256>>>(ctx, Wout, bout, out, BN, DD, DD);
}

// round 5
// speedup vs baseline: 1.7134x; 1.7134x over previous
#include <cuda_runtime.h>
#include <cuda_bf16.h>
#include <math.h>
#include <stdint.h>

//  B=4, N=4096, D=1024, H=16, M=256, dk=64
#define BB   4
#define NN   4096
#define DD   1024
#define HH   16
#define MM   256
#define DKK  64
#define BN   (BB*NN)          // 16384
#define BH   (BB*HH)          // 64
#define D3   (3*DD)           // 3072

#define INV_SQRT_M 0.0625f
#define EPS_DENOM  1e-6f

// ---------------- device scratch (no allocations allowed) -----------------
// ctx hi/lo bf16 alias the front of g_Kf: Kf (67 MB) is dead after s_kernel;
// ctx_kernel writes ch/cl strictly after reduce_kernel (stream order), and
// ch+cl = 64 MB fit. ~437 MB total statics.
__device__ float g_qkv[(size_t)BN * D3];              // 201 MB
__device__ float g_Qf [(size_t)BH * NN * MM];         // 67 MB
__device__ float g_Kf [(size_t)BH * NN * MM];         // 67 MB (tail reused for ctx)
__device__ float g_Spart[(size_t)8 * BH * MM * DKK];  // 32 MB
__device__ float g_Kpart[(size_t)8 * BH * MM];        // 512 KB
__device__ float g_S  [(size_t)BH * MM * DKK];        // 4 MB
__device__ float g_Ksum[(size_t)BH * MM];             // 64 KB
__device__ float g_valid[(size_t)BN];
__device__ int   g_mask_mode;
// bf16 hi/lo splits for tensor-core GEMMs
__device__ __nv_bfloat16 g_xh[(size_t)BN * DD];       // 32 MB
__device__ __nv_bfloat16 g_xl[(size_t)BN * DD];       // 32 MB
__device__ __nv_bfloat16 g_Wqh[(size_t)D3 * DD];      // 6 MB
__device__ __nv_bfloat16 g_Wql[(size_t)D3 * DD];      // 6 MB
__device__ __nv_bfloat16 g_Woh[(size_t)DD * DD];      // 2 MB
__device__ __nv_bfloat16 g_Wol[(size_t)DD * DD];      // 2 MB

// ===========================================================================
// Mask dtype detection + expansion (int32 / float32 / uint8 robust)
// ===========================================================================
__global__ void mask_detect_kernel(const unsigned int* __restrict__ mw)
{
    __shared__ int sawF, sawB;
    if (threadIdx.x == 0) { sawF = 0; sawB = 0; }
    __syncthreads();
    for (int i = threadIdx.x; i < 4096; i += 256) {
        unsigned int v = mw[i];
        if (v == 0x3F800000u) atomicOr(&sawF, 1);
        else if (v != 0u && v != 1u) atomicOr(&sawB, 1);
    }
    __syncthreads();
    if (threadIdx.x == 0) g_mask_mode = sawF ? 1 : (sawB ? 2 : 0);
}

__global__ void mask_expand_kernel(const void* __restrict__ m, float* __restrict__ valid)
{
    int i = blockIdx.x * 256 + threadIdx.x;
    if (i >= BN) return;
    int mode = g_mask_mode;
    bool pad;
    if (mode == 0)      pad = ((const int*)m)[i] != 0;
    else if (mode == 1) pad = ((const float*)m)[i] != 0.0f;
    else                pad = ((const unsigned char*)m)[i] != 0;
    valid[i] = pad ? 0.0f : 1.0f;
}

// fp32 -> (hi, lo) bf16 split
__global__ void convert_split_kernel(const float* __restrict__ src,
                                     __nv_bfloat16* __restrict__ hi,
                                     __nv_bfloat16* __restrict__ lo, int n)
{
    int i = blockIdx.x * 256 + threadIdx.x;
    if (i >= n) return;
    float v = src[i];
    __nv_bfloat16 h = __float2bfloat16(v);
    hi[i] = h;
    lo[i] = __float2bfloat16(v - __bfloat162float(h));
}

// ===========================================================================
// bf16x3 tensor-core GEMM: C = A(MxK) * Bt(NxK)^T + bias, fp32 out.
// A,Bt supplied as hi/lo bf16. Block 128x128, BK=32, 8 warps (64x32 each).
// mma.sync.aligned.m16n8k16.row.col.f32.bf16.bf16.f32, 3 passes (hh, hl, lh).
// ===========================================================================
__device__ __forceinline__ void mma_bf16(float* d, const uint32_t* a, const uint32_t* b)
{
    asm volatile(
        "mma.sync.aligned.m16n8k16.row.col.f32.bf16.bf16.f32 "
        "{%0,%1,%2,%3},{%4,%5,%6,%7},{%8,%9},{%0,%1,%2,%3};"
        : "+f"(d[0]), "+f"(d[1]), "+f"(d[2]), "+f"(d[3])
        : "r"(a[0]), "r"(a[1]), "r"(a[2]), "r"(a[3]), "r"(b[0]), "r"(b[1]));
}

__global__ __launch_bounds__(256, 2) void gemm_bf16x3_nt(
    const __nv_bfloat16* __restrict__ Ahi, const __nv_bfloat16* __restrict__ Alo,
    const __nv_bfloat16* __restrict__ Bhi, const __nv_bfloat16* __restrict__ Blo,
    const float* __restrict__ bias, float* __restrict__ C,
    int Nd, int Kd)
{
    // row stride 20 u32 (=40 bf16): bank sets per 8-row group are disjoint
    __shared__ uint32_t As_h[128][20];
    __shared__ uint32_t As_l[128][20];
    __shared__ uint32_t Bs_h[128][20];
    __shared__ uint32_t Bs_l[128][20];

    const int tid  = threadIdx.x;
    const int lane = tid & 31;
    const int w    = tid >> 5;
    const int wm   = (w >> 2) * 64;      // warp M offset (0 or 64)
    const int wn   = (w & 3) * 32;       // warp N offset
    const int q    = lane & 3;           // thread-in-group
    const int g    = lane >> 2;          // group id
    const int rowBase = blockIdx.y * 128;
    const int colBase = blockIdx.x * 128;

    float acc[4][4][4];
#pragma unroll
    for (int mt = 0; mt < 4; mt++)
#pragma unroll
        for (int nt = 0; nt < 4; nt++)
#pragma unroll
            for (int e = 0; e < 4; e++) acc[mt][nt][e] = 0.f;

    for (int k0 = 0; k0 < Kd; k0 += 32) {
#pragma unroll
        for (int t = 0; t < 2; t++) {
            int v  = tid + t * 256;          // 0..511
            int r  = v >> 2;                 // 0..127
            int ch = v & 3;                  // 0..3 (uint4 chunk, 8 bf16)
            size_t ga = (size_t)(rowBase + r) * Kd + k0 + ch * 8;
            size_t gb = (size_t)(colBase + r) * Kd + k0 + ch * 8;
            *reinterpret_cast<uint4*>(&As_h[r][ch * 4]) = *reinterpret_cast<const uint4*>(Ahi + ga);
            *reinterpret_cast<uint4*>(&As_l[r][ch * 4]) = *reinterpret_cast<const uint4*>(Alo + ga);
            *reinterpret_cast<uint4*>(&Bs_h[r][ch * 4]) = *reinterpret_cast<const uint4*>(Bhi + gb);
            *reinterpret_cast<uint4*>(&Bs_l[r][ch * 4]) = *reinterpret_cast<const uint4*>(Blo + gb);
        }
        __syncthreads();

#pragma unroll
        for (int kko = 0; kko < 16; kko += 8) {      // two k16 halves (u32 offset)
            uint32_t bh[4][2], bl[4][2];
#pragma unroll
            for (int nt = 0; nt < 4; nt++) {
                int n = wn + nt * 8 + g;
                bh[nt][0] = Bs_h[n][q + kko];
                bh[nt][1] = Bs_h[n][q + 4 + kko];
                bl[nt][0] = Bs_l[n][q + kko];
                bl[nt][1] = Bs_l[n][q + 4 + kko];
            }
#pragma unroll
            for (int mt = 0; mt < 4; mt++) {
                int r0 = wm + mt * 16 + g;
                uint32_t ah[4], al[4];
                ah[0] = As_h[r0][q + kko];     ah[1] = As_h[r0 + 8][q + kko];
                ah[2] = As_h[r0][q + 4 + kko]; ah[3] = As_h[r0 + 8][q + 4 + kko];
                al[0] = As_l[r0][q + kko];     al[1] = As_l[r0 + 8][q + kko];
                al[2] = As_l[r0][q + 4 + kko]; al[3] = As_l[r0 + 8][q + 4 + kko];
#pragma unroll
                for (int nt = 0; nt < 4; nt++) {
                    mma_bf16(acc[mt][nt], ah, bh[nt]);   // hi*hi
                    mma_bf16(acc[mt][nt], ah, bl[nt]);   // hi*lo
                    mma_bf16(acc[mt][nt], al, bh[nt]);   // lo*hi
                }
            }
        }
        __syncthreads();
    }

#pragma unroll
    for (int mt = 0; mt < 4; mt++) {
        int r0 = rowBase + wm + mt * 16 + g;
#pragma unroll
        for (int nt = 0; nt < 4; nt++) {
            int c = colBase + wn + nt * 8 + q * 2;
            float b0 = bias[c], b1 = bias[c + 1];
            float2* p0 = reinterpret_cast<float2*>(C + (size_t)r0 * Nd + c);
            float2* p1 = reinterpret_cast<float2*>(C + (size_t)(r0 + 8) * Nd + c);
            *p0 = make_float2(acc[mt][nt][0] + b0, acc[mt][nt][1] + b1);
            *p1 = make_float2(acc[mt][nt][2] + b0, acc[mt][nt][3] + b1);
        }
    }
}

// ===========================================================================
// phi kernel: proj = T @ omega^T, out = exp(proj - rowmax - 0.5|t|^2)/16
// ===========================================================================
__global__ __launch_bounds__(256) void phi_kernel(
    const float* __restrict__ qkv, const float* __restrict__ omega,
    const float* __restrict__ valid,
    float* __restrict__ Qf, float* __restrict__ Kf)
{
    const int ntile = blockIdx.x;
    const int bh    = blockIdx.y;
    const int isK   = blockIdx.z;
    const int b = bh >> 4, h = bh & 15;
    const int n0 = ntile * 64;
    const int tid = threadIdx.x;
    const int ty = tid >> 4, tx = tid & 15;

    __shared__ float Ts[16][68];
    __shared__ float Om[16][257];
    __shared__ float validS[64];

    if (tid < 64)
        validS[tid] = valid[b * NN + n0 + tid];

    const float* src = qkv + ((size_t)(b * NN + n0)) * D3 + (size_t)isK * DD + h * DKK;
    const float* om  = omega + (size_t)h * MM * DKK;

    float acc[4][16];
    float sq[4];
#pragma unroll
    for (int i = 0; i < 4; i++) {
        sq[i] = 0.f;
#pragma unroll
        for (int j = 0; j < 16; j++) acc[i][j] = 0.f;
    }

    for (int kc = 0; kc < 4; kc++) {
        __syncthreads();
        for (int i = tid; i < 64 * 16; i += 256) {
            int r = i >> 4, kk = i & 15;
            float v = src[(size_t)r * D3 + kc * 16 + kk];
            if (!isK) v *= validS[r];
            Ts[kk][r] = v;
        }
        for (int i = tid; i < 256 * 16; i += 256) {
            int m = i >> 4, kk = i & 15;
            Om[kk][m] = om[(size_t)m * DKK + kc * 16 + kk];
        }
        __syncthreads();
#pragma unroll
        for (int k = 0; k < 16; k++) {
            float a[4];
#pragma unroll
            for (int i = 0; i < 4; i++) {
                a[i] = Ts[k][ty + i * 16];
                sq[i] += a[i] * a[i];
            }
#pragma unroll
            for (int j = 0; j < 16; j++) {
                float bx = Om[k][tx + j * 16];
#pragma unroll
                for (int i = 0; i < 4; i++) acc[i][j] += a[i] * bx;
            }
        }
    }

    float base[4];
#pragma unroll
    for (int i = 0; i < 4; i++) {
        float mx = acc[i][0];
#pragma unroll
        for (int j = 1; j < 16; j++) mx = fmaxf(mx, acc[i][j]);
#pragma unroll
        for (int s = 1; s < 16; s <<= 1)
            mx = fmaxf(mx, __shfl_xor_sync(0xffffffffu, mx, s));
        base[i] = -mx - 0.5f * sq[i];
    }

    float* dst = (isK ? Kf : Qf) + ((size_t)bh * NN + n0) * MM;
#pragma unroll
    for (int i = 0; i < 4; i++) {
        int r = ty + i * 16;
        float post = isK ? (INV_SQRT_M * validS[r]) : INV_SQRT_M;
#pragma unroll
        for (int j = 0; j < 16; j++) {
            dst[(size_t)r * MM + tx + j * 16] = expf(acc[i][j] + base[i]) * post;
        }
    }
}

// ===========================================================================
// S kernel (split-K, deterministic)
// ===========================================================================
__global__ __launch_bounds__(256) void s_kernel(
    const float* __restrict__ Kf, const float* __restrict__ qkv,
    float* __restrict__ Spart, float* __restrict__ Kpart)
{
    const int chunk = blockIdx.x;
    const int bh    = blockIdx.y;
    const int b = bh >> 4, h = bh & 15;
    const int n0 = chunk * 512;
    const int tid = threadIdx.x;
    const int mg = tid >> 3;
    const int dg = tid & 7;

    __shared__ float Ks[16][256];
    __shared__ float Vs[16][64];

    float acc[8][8];
    float ks[8];
#pragma unroll
    for (int i = 0; i < 8; i++) {
        ks[i] = 0.f;
#pragma unroll
        for (int j = 0; j < 8; j++) acc[i][j] = 0.f;
    }

    const float* kf   = Kf + ((size_t)bh * NN + n0) * MM;
    const float* vsrc = qkv + ((size_t)(b * NN + n0)) * D3 + 2 * DD + h * DKK;

    for (int sub = 0; sub < 32; sub++) {
        __syncthreads();
        for (int i = tid; i < 16 * 256; i += 256) {
            int n = i >> 8, m = i & 255;
            Ks[n][m] = kf[(size_t)(sub * 16 + n) * MM + m];
        }
        for (int i = tid; i < 16 * 64; i += 256) {
            int n = i >> 6, d = i & 63;
            Vs[n][d] = vsrc[(size_t)(sub * 16 + n) * D3 + d];
        }
        __syncthreads();
#pragma unroll
        for (int n = 0; n < 16; n++) {
            float a[8], bx[8];
#pragma unroll
            for (int i = 0; i < 8; i++) a[i] = Ks[n][mg + i * 32];
#pragma unroll
            for (int j = 0; j < 8; j++) bx[j] = Vs[n][dg + j * 8];
#pragma unroll
            for (int i = 0; i < 8; i++) {
                ks[i] += a[i];
#pragma unroll
                for (int j = 0; j < 8; j++) acc[i][j] += a[i] * bx[j];
            }
        }
    }

    float* Sp = Spart + ((size_t)chunk * BH + bh) * (MM * DKK);
    float* Kp = Kpart + ((size_t)chunk * BH + bh) * MM;
#pragma unroll
    for (int i = 0; i < 8; i++) {
        int m = mg + i * 32;
#pragma unroll
        for (int j = 0; j < 8; j++)
            Sp[m * DKK + dg + j * 8] = acc[i][j];
        if (dg == 0) Kp[m] = ks[i];
    }
}

__global__ __launch_bounds__(256) void reduce_kernel(
    const float* __restrict__ Spart, const float* __restrict__ Kpart,
    float* __restrict__ S, float* __restrict__ Ksum)
{
    int i = blockIdx.x * 256 + threadIdx.x;
    const size_t SSZ = (size_t)BH * MM * DKK;
    const size_t KSZ = (size_t)BH * MM;
    if (i < (int)SSZ) {
        float s = 0.f;
#pragma unroll
        for (int c = 0; c < 8; c++) s += Spart[(size_t)c * SSZ + i];
        S[i] = s;
    }
    if (i < (int)KSZ) {
        float s = 0.f;
#pragma unroll
        for (int c = 0; c < 8; c++) s += Kpart[(size_t)c * KSZ + i];
        Ksum[i] = s;
    }
}

// ===========================================================================
// ctx kernel: num = Qf @ S; den = Qf . Ksum; writes bf16 hi/lo ctx directly.
// ===========================================================================
__global__ __launch_bounds__(256) void ctx_kernel(
    const float* __restrict__ Qf, const float* __restrict__ S,
    const float* __restrict__ Ksum, const float* __restrict__ valid,
    __nv_bfloat16* __restrict__ ctxh, __nv_bfloat16* __restrict__ ctxl)
{
    const int ntile = blockIdx.x;
    const int bh    = blockIdx.y;
    const int b = bh >> 4, h = bh & 15;
    const int n0 = ntile * 64;
    const int tid = threadIdx.x;
    const int ty = tid >> 4, tx = tid & 15;

    __shared__ float Qs[64][65];
    __shared__ float Ss[64][65];
    __shared__ float Ksm[256];
    __shared__ float validS[64];

    if (tid < 64) validS[tid] = valid[b * NN + n0 + tid];
    Ksm[tid] = Ksum[bh * MM + tid];

    float acc[4][4];
    float den[4];
#pragma unroll
    for (int i = 0; i < 4; i++) {
        den[i] = 0.f;
#pragma unroll
        for (int j = 0; j < 4; j++) acc[i][j] = 0.f;
    }

    const float* qf = Qf + ((size_t)bh * NN + n0) * MM;
    const float* Sp = S + (size_t)bh * MM * DKK;

    for (int mc = 0; mc < 4; mc++) {
        __syncthreads();
        for (int i = tid; i < 64 * 64; i += 256) {
            int r = i >> 6, m = i & 63;
            Qs[r][m] = qf[(size_t)r * MM + mc * 64 + m];
        }
        for (int i = tid; i < 64 * 64; i += 256) {
            int m = i >> 6, d = i & 63;
            Ss[m][d] = Sp[(mc * 64 + m) * DKK + d];
        }
        __syncthreads();
#pragma unroll 8
        for (int m = 0; m < 64; m++) {
            float kv = Ksm[mc * 64 + m];
            float a[4], bx[4];
#pragma unroll
            for (int i = 0; i < 4; i++) a[i] = Qs[ty + i * 16][m];
#pragma unroll
            for (int j = 0; j < 4; j++) bx[j] = Ss[m][tx + j * 16];
#pragma unroll
            for (int i = 0; i < 4; i++) {
                den[i] += a[i] * kv;
#pragma unroll
                for (int j = 0; j < 4; j++) acc[i][j] += a[i] * bx[j];
            }
        }
    }

#pragma unroll
    for (int i = 0; i < 4; i++) {
        int r = ty + i * 16;
        float scale = validS[r] / (den[i] + EPS_DENOM);
        size_t base = ((size_t)(b * NN) + n0 + r) * DD + h * DKK;
#pragma unroll
        for (int j = 0; j < 4; j++) {
            float v = acc[i][j] * scale;
            __nv_bfloat16 hh = __float2bfloat16(v);
            ctxh[base + tx + j * 16] = hh;
            ctxl[base + tx + j * 16] = __float2bfloat16(v - __bfloat162float(hh));
        }
    }
}

// ===========================================================================
extern "C" void kernel_launch(void* const* d_in, const int* in_sizes, int n_in,
                              void* d_out, int out_size)
{
    const float* x     = (const float*)d_in[0];
    const float* Wqkv  = (const float*)d_in[1];
    const float* bqkv  = (const float*)d_in[2];
    const float* Wout  = (const float*)d_in[3];
    const float* bout  = (const float*)d_in[4];
    const float* omega = (const float*)d_in[5];
    const void*  maskp = d_in[6];
    float* out = (float*)d_out;

    float *qkv, *Qf, *Kf, *Spart, *Kpart, *S, *Ksum, *valid;
    __nv_bfloat16 *xh, *xl, *Wqh, *Wql, *Woh, *Wol;
    cudaGetSymbolAddress((void**)&qkv,   g_qkv);
    cudaGetSymbolAddress((void**)&Qf,    g_Qf);
    cudaGetSymbolAddress((void**)&Kf,    g_Kf);
    cudaGetSymbolAddress((void**)&Spart, g_Spart);
    cudaGetSymbolAddress((void**)&Kpart, g_Kpart);
    cudaGetSymbolAddress((void**)&S,     g_S);
    cudaGetSymbolAddress((void**)&Ksum,  g_Ksum);
    cudaGetSymbolAddress((void**)&valid, g_valid);
    cudaGetSymbolAddress((void**)&xh,  g_xh);
    cudaGetSymbolAddress((void**)&xl,  g_xl);
    cudaGetSymbolAddress((void**)&Wqh, g_Wqh);
    cudaGetSymbolAddress((void**)&Wql, g_Wql);
    cudaGetSymbolAddress((void**)&Woh, g_Woh);
    cudaGetSymbolAddress((void**)&Wol, g_Wol);
    // ctx hi/lo alias g_Kf (dead after s_kernel; written after reduce_kernel)
    __nv_bfloat16* ch = reinterpret_cast<__nv_bfloat16*>(Kf);
    __nv_bfloat16* cl = ch + (size_t)BN * DD;

    // 0) canonicalize mask + bf16 hi/lo splits of GEMM operands
    mask_detect_kernel<<<1, 256>>>((const unsigned int*)maskp);
    mask_expand_kernel<<<BN / 256, 256>>>(maskp, valid);
    convert_split_kernel<<<(BN * DD) / 256, 256>>>(x, xh, xl, BN * DD);
    convert_split_kernel<<<(D3 * DD) / 256, 256>>>(Wqkv, Wqh, Wql, D3 * DD);
    convert_split_kernel<<<(DD * DD) / 256, 256>>>(Wout, Woh, Wol, DD * DD);

    // 1) qkv = x @ Wqkv^T + bqkv   (tensor cores, bf16x3)
    gemm_bf16x3_nt<<<dim3(D3 / 128, BN / 128), 256>>>(xh, xl, Wqh, Wql, bqkv, qkv, D3, DD);

    // 2) phi for Q and K
    phi_kernel<<<dim3(NN / 64, BH, 2), 256>>>(qkv, omega, valid, Qf, Kf);

    // 3) S = Kf^T V (split-K + deterministic reduce)
    s_kernel<<<dim3(8, BH), 256>>>(Kf, qkv, Spart, Kpart);
    reduce_kernel<<<4096, 256>>>(Spart, Kpart, S, Ksum);

    // 4) ctx (writes bf16 hi/lo directly into the Kf alias)
    ctx_kernel<<<dim3(NN / 64, BH), 256>>>(Qf, S, Ksum, valid, ch, cl);

    // 5) out = ctx @ Wout^T + bout (tensor cores, bf16x3)
    gemm_bf16x3_nt<<<dim3(DD / 128, BN / 128), 256>>>(ch, cl, Woh, Wol, bout, out, DD, DD);
}

// round 6
// speedup vs baseline: 1.9156x; 1.1180x over previous
#include <cuda_runtime.h>
#include <cuda_bf16.h>
#include <math.h>
#include <stdint.h>

//  B=4, N=4096, D=1024, H=16, M=256, dk=64
#define BB   4
#define NN   4096
#define DD   1024
#define HH   16
#define MM   256
#define DKK  64
#define BN   (BB*NN)          // 16384
#define BH   (BB*HH)          // 64
#define D3   (3*DD)           // 3072

#define INV_SQRT_M 0.0625f
#define EPS_DENOM  1e-6f

// ---------------- device scratch (no allocations allowed) -----------------
__device__ float g_qkv[(size_t)BN * D3];                 // 201 MB
__device__ __nv_bfloat16 g_QfH[(size_t)BH * NN * MM];    // 134 MB
__device__ __nv_bfloat16 g_QfL[(size_t)BH * NN * MM];
__device__ __nv_bfloat16 g_KfH[(size_t)BH * NN * MM];
__device__ __nv_bfloat16 g_KfL[(size_t)BH * NN * MM];
__device__ float g_Spart[(size_t)8 * BH * MM * 64];      // 33.5 MB
__device__ float g_Kpart[(size_t)8 * BH * MM];
__device__ __nv_bfloat16 g_StH[(size_t)BH * 72 * MM];    // S^T + Ksum row, bf16 hi
__device__ __nv_bfloat16 g_StL[(size_t)BH * 72 * MM];
__device__ float g_valid[(size_t)BN];
__device__ int   g_mask_mode;
__device__ __nv_bfloat16 g_xh[(size_t)BN * DD];
__device__ __nv_bfloat16 g_xl[(size_t)BN * DD];
__device__ __nv_bfloat16 g_Wqh[(size_t)D3 * DD];
__device__ __nv_bfloat16 g_Wql[(size_t)D3 * DD];
__device__ __nv_bfloat16 g_Woh[(size_t)DD * DD];
__device__ __nv_bfloat16 g_Wol[(size_t)DD * DD];
__device__ __nv_bfloat16 g_Vh[(size_t)BN * DD];
__device__ __nv_bfloat16 g_Vl[(size_t)BN * DD];
__device__ __nv_bfloat16 g_ch[(size_t)BN * DD];
__device__ __nv_bfloat16 g_cl[(size_t)BN * DD];

// ---------------- ldmatrix / mma helpers -----------------------------------
__device__ __forceinline__ uint32_t smaddr(const void* p) {
    return (uint32_t)__cvta_generic_to_shared(p);
}
__device__ __forceinline__ void ldsm_x4(uint32_t* r, uint32_t a) {
    asm volatile("ldmatrix.sync.aligned.m8n8.x4.shared.b16 {%0,%1,%2,%3}, [%4];"
        : "=r"(r[0]), "=r"(r[1]), "=r"(r[2]), "=r"(r[3]) : "r"(a));
}
__device__ __forceinline__ void ldsm_x4_t(uint32_t* r, uint32_t a) {
    asm volatile("ldmatrix.sync.aligned.m8n8.x4.trans.shared.b16 {%0,%1,%2,%3}, [%4];"
        : "=r"(r[0]), "=r"(r[1]), "=r"(r[2]), "=r"(r[3]) : "r"(a));
}
__device__ __forceinline__ void ldsm_x2(uint32_t* r, uint32_t a) {
    asm volatile("ldmatrix.sync.aligned.m8n8.x2.shared.b16 {%0,%1}, [%2];"
        : "=r"(r[0]), "=r"(r[1]) : "r"(a));
}
__device__ __forceinline__ void ldsm_x2_t(uint32_t* r, uint32_t a) {
    asm volatile("ldmatrix.sync.aligned.m8n8.x2.trans.shared.b16 {%0,%1}, [%2];"
        : "=r"(r[0]), "=r"(r[1]) : "r"(a));
}
__device__ __forceinline__ void mma_bf16(float* d, const uint32_t* a, const uint32_t* b)
{
    asm volatile(
        "mma.sync.aligned.m16n8k16.row.col.f32.bf16.bf16.f32 "
        "{%0,%1,%2,%3},{%4,%5,%6,%7},{%8,%9},{%0,%1,%2,%3};"
        : "+f"(d[0]), "+f"(d[1]), "+f"(d[2]), "+f"(d[3])
        : "r"(a[0]), "r"(a[1]), "r"(a[2]), "r"(a[3]), "r"(b[0]), "r"(b[1]));
}

// ===========================================================================
// Mask dtype detection + expansion (int32 / float32 / uint8 robust)
// ===========================================================================
__global__ void mask_detect_kernel(const unsigned int* __restrict__ mw)
{
    __shared__ int sawF, sawB;
    if (threadIdx.x == 0) { sawF = 0; sawB = 0; }
    __syncthreads();
    for (int i = threadIdx.x; i < 4096; i += 256) {
        unsigned int v = mw[i];
        if (v == 0x3F800000u) atomicOr(&sawF, 1);
        else if (v != 0u && v != 1u) atomicOr(&sawB, 1);
    }
    __syncthreads();
    if (threadIdx.x == 0) g_mask_mode = sawF ? 1 : (sawB ? 2 : 0);
}

__global__ void mask_expand_kernel(const void* __restrict__ m, float* __restrict__ valid)
{
    int i = blockIdx.x * 256 + threadIdx.x;
    if (i >= BN) return;
    int mode = g_mask_mode;
    bool pad;
    if (mode == 0)      pad = ((const int*)m)[i] != 0;
    else if (mode == 1) pad = ((const float*)m)[i] != 0.0f;
    else                pad = ((const unsigned char*)m)[i] != 0;
    valid[i] = pad ? 0.0f : 1.0f;
}

// fp32 -> (hi, lo) bf16 split (contiguous)
__global__ void convert_split_kernel(const float* __restrict__ src,
                                     __nv_bfloat16* __restrict__ hi,
                                     __nv_bfloat16* __restrict__ lo, int n)
{
    int i = blockIdx.x * 256 + threadIdx.x;
    if (i >= n) return;
    float v = src[i];
    __nv_bfloat16 h = __float2bfloat16(v);
    hi[i] = h;
    lo[i] = __float2bfloat16(v - __bfloat162float(h));
}

// split V out of qkv (columns 2048..3071) into [BN][1024] bf16 hi/lo
__global__ void convert_v_kernel(const float* __restrict__ qkv,
                                 __nv_bfloat16* __restrict__ Vh,
                                 __nv_bfloat16* __restrict__ Vl)
{
    int i = blockIdx.x * 256 + threadIdx.x;   // 0 .. BN*1024
    int row = i >> 10, col = i & 1023;
    float v = qkv[(size_t)row * D3 + 2 * DD + col];
    __nv_bfloat16 h = __float2bfloat16(v);
    Vh[i] = h;
    Vl[i] = __float2bfloat16(v - __bfloat162float(h));
}

// ===========================================================================
// bf16x3 tensor-core GEMM (unchanged from round 5)
// ===========================================================================
__global__ __launch_bounds__(256, 2) void gemm_bf16x3_nt(
    const __nv_bfloat16* __restrict__ Ahi, const __nv_bfloat16* __restrict__ Alo,
    const __nv_bfloat16* __restrict__ Bhi, const __nv_bfloat16* __restrict__ Blo,
    const float* __restrict__ bias, float* __restrict__ C,
    int Nd, int Kd)
{
    __shared__ uint32_t As_h[128][20];
    __shared__ uint32_t As_l[128][20];
    __shared__ uint32_t Bs_h[128][20];
    __shared__ uint32_t Bs_l[128][20];

    const int tid  = threadIdx.x;
    const int lane = tid & 31;
    const int w    = tid >> 5;
    const int wm   = (w >> 2) * 64;
    const int wn   = (w & 3) * 32;
    const int q    = lane & 3;
    const int g    = lane >> 2;
    const int rowBase = blockIdx.y * 128;
    const int colBase = blockIdx.x * 128;

    float acc[4][4][4];
#pragma unroll
    for (int mt = 0; mt < 4; mt++)
#pragma unroll
        for (int nt = 0; nt < 4; nt++)
#pragma unroll
            for (int e = 0; e < 4; e++) acc[mt][nt][e] = 0.f;

    for (int k0 = 0; k0 < Kd; k0 += 32) {
#pragma unroll
        for (int t = 0; t < 2; t++) {
            int v  = tid + t * 256;
            int r  = v >> 2;
            int ch = v & 3;
            size_t ga = (size_t)(rowBase + r) * Kd + k0 + ch * 8;
            size_t gb = (size_t)(colBase + r) * Kd + k0 + ch * 8;
            *reinterpret_cast<uint4*>(&As_h[r][ch * 4]) = *reinterpret_cast<const uint4*>(Ahi + ga);
            *reinterpret_cast<uint4*>(&As_l[r][ch * 4]) = *reinterpret_cast<const uint4*>(Alo + ga);
            *reinterpret_cast<uint4*>(&Bs_h[r][ch * 4]) = *reinterpret_cast<const uint4*>(Bhi + gb);
            *reinterpret_cast<uint4*>(&Bs_l[r][ch * 4]) = *reinterpret_cast<const uint4*>(Blo + gb);
        }
        __syncthreads();
#pragma unroll
        for (int kko = 0; kko < 16; kko += 8) {
            uint32_t bh[4][2], bl[4][2];
#pragma unroll
            for (int nt = 0; nt < 4; nt++) {
                int n = wn + nt * 8 + g;
                bh[nt][0] = Bs_h[n][q + kko];
                bh[nt][1] = Bs_h[n][q + 4 + kko];
                bl[nt][0] = Bs_l[n][q + kko];
                bl[nt][1] = Bs_l[n][q + 4 + kko];
            }
#pragma unroll
            for (int mt = 0; mt < 4; mt++) {
                int r0 = wm + mt * 16 + g;
                uint32_t ah[4], al[4];
                ah[0] = As_h[r0][q + kko];     ah[1] = As_h[r0 + 8][q + kko];
                ah[2] = As_h[r0][q + 4 + kko]; ah[3] = As_h[r0 + 8][q + 4 + kko];
                al[0] = As_l[r0][q + kko];     al[1] = As_l[r0 + 8][q + kko];
                al[2] = As_l[r0][q + 4 + kko]; al[3] = As_l[r0 + 8][q + 4 + kko];
#pragma unroll
                for (int nt = 0; nt < 4; nt++) {
                    mma_bf16(acc[mt][nt], ah, bh[nt]);
                    mma_bf16(acc[mt][nt], ah, bl[nt]);
                    mma_bf16(acc[mt][nt], al, bh[nt]);
                }
            }
        }
        __syncthreads();
    }

#pragma unroll
    for (int mt = 0; mt < 4; mt++) {
        int r0 = rowBase + wm + mt * 16 + g;
#pragma unroll
        for (int nt = 0; nt < 4; nt++) {
            int c = colBase + wn + nt * 8 + q * 2;
            float b0 = bias[c], b1 = bias[c + 1];
            float2* p0 = reinterpret_cast<float2*>(C + (size_t)r0 * Nd + c);
            float2* p1 = reinterpret_cast<float2*>(C + (size_t)(r0 + 8) * Nd + c);
            *p0 = make_float2(acc[mt][nt][0] + b0, acc[mt][nt][1] + b1);
            *p1 = make_float2(acc[mt][nt][2] + b0, acc[mt][nt][3] + b1);
        }
    }
}

// ===========================================================================
// phi kernel: writes Qf/Kf as bf16 hi/lo arrays
// ===========================================================================
__global__ __launch_bounds__(256) void phi_kernel(
    const float* __restrict__ qkv, const float* __restrict__ omega,
    const float* __restrict__ valid,
    __nv_bfloat16* __restrict__ QfH, __nv_bfloat16* __restrict__ QfL,
    __nv_bfloat16* __restrict__ KfH, __nv_bfloat16* __restrict__ KfL)
{
    const int ntile = blockIdx.x;
    const int bh    = blockIdx.y;
    const int isK   = blockIdx.z;
    const int b = bh >> 4, h = bh & 15;
    const int n0 = ntile * 64;
    const int tid = threadIdx.x;
    const int ty = tid >> 4, tx = tid & 15;

    __shared__ float Ts[16][68];
    __shared__ float Om[16][257];
    __shared__ float validS[64];

    if (tid < 64)
        validS[tid] = valid[b * NN + n0 + tid];

    const float* src = qkv + ((size_t)(b * NN + n0)) * D3 + (size_t)isK * DD + h * DKK;
    const float* om  = omega + (size_t)h * MM * DKK;

    float acc[4][16];
    float sq[4];
#pragma unroll
    for (int i = 0; i < 4; i++) {
        sq[i] = 0.f;
#pragma unroll
        for (int j = 0; j < 16; j++) acc[i][j] = 0.f;
    }

    for (int kc = 0; kc < 4; kc++) {
        __syncthreads();
        for (int i = tid; i < 64 * 16; i += 256) {
            int r = i >> 4, kk = i & 15;
            float v = src[(size_t)r * D3 + kc * 16 + kk];
            if (!isK) v *= validS[r];
            Ts[kk][r] = v;
        }
        for (int i = tid; i < 256 * 16; i += 256) {
            int m = i >> 4, kk = i & 15;
            Om[kk][m] = om[(size_t)m * DKK + kc * 16 + kk];
        }
        __syncthreads();
#pragma unroll
        for (int k = 0; k < 16; k++) {
            float a[4];
#pragma unroll
            for (int i = 0; i < 4; i++) {
                a[i] = Ts[k][ty + i * 16];
                sq[i] += a[i] * a[i];
            }
#pragma unroll
            for (int j = 0; j < 16; j++) {
                float bx = Om[k][tx + j * 16];
#pragma unroll
                for (int i = 0; i < 4; i++) acc[i][j] += a[i] * bx;
            }
        }
    }

    float base[4];
#pragma unroll
    for (int i = 0; i < 4; i++) {
        float mx = acc[i][0];
#pragma unroll
        for (int j = 1; j < 16; j++) mx = fmaxf(mx, acc[i][j]);
#pragma unroll
        for (int s = 1; s < 16; s <<= 1)
            mx = fmaxf(mx, __shfl_xor_sync(0xffffffffu, mx, s));
        base[i] = -mx - 0.5f * sq[i];
    }

    size_t off = ((size_t)bh * NN + n0) * MM;
    __nv_bfloat16* dh = (isK ? KfH : QfH) + off;
    __nv_bfloat16* dl = (isK ? KfL : QfL) + off;
#pragma unroll
    for (int i = 0; i < 4; i++) {
        int r = ty + i * 16;
        float post = isK ? (INV_SQRT_M * validS[r]) : INV_SQRT_M;
#pragma unroll
        for (int j = 0; j < 16; j++) {
            float v = expf(acc[i][j] + base[i]) * post;
            __nv_bfloat16 hh = __float2bfloat16(v);
            size_t idx = (size_t)r * MM + tx + j * 16;
            dh[idx] = hh;
            dl[idx] = __float2bfloat16(v - __bfloat162float(hh));
        }
    }
}

// ===========================================================================
// s_kernel_mma: per (chunk of 512 n, bh): Spart[m<256][d<64] = Kf^T V, with a
// ones-column at d=64 producing Kpart. bf16x3 via mma + ldmatrix.trans.
// 8 warps: 4 m-groups (64) x 2 d-groups (32 / 40 incl. ones col).
// ===========================================================================
__global__ __launch_bounds__(256) void s_kernel_mma(
    const __nv_bfloat16* __restrict__ KfH, const __nv_bfloat16* __restrict__ KfL,
    const __nv_bfloat16* __restrict__ Vh,  const __nv_bfloat16* __restrict__ Vl,
    float* __restrict__ Spart, float* __restrict__ Kpart)
{
    __shared__ __align__(16) uint8_t KsH[32 * 528];
    __shared__ __align__(16) uint8_t KsL[32 * 528];
    __shared__ __align__(16) uint8_t VsH[32 * 176];
    __shared__ __align__(16) uint8_t VsL[32 * 176];

    const int chunk = blockIdx.x;     // 0..7
    const int bh    = blockIdx.y;     // 0..63
    const int b = bh >> 4, h = bh & 15;
    const int tid = threadIdx.x;
    const int lane = tid & 31;
    const int w = tid >> 5;
    const int wm = (w >> 1) * 64;
    const int dgrp = w & 1;
    const int dbase = dgrp ? 32 : 0;
    const int NT = dgrp ? 5 : 4;

    float acc[4][5][4];
#pragma unroll
    for (int mt = 0; mt < 4; mt++)
#pragma unroll
        for (int nt = 0; nt < 5; nt++)
#pragma unroll
            for (int e = 0; e < 4; e++) acc[mt][nt][e] = 0.f;

    const uint4 ones_hi = make_uint4(0x00003F80u, 0u, 0u, 0u);  // bf16 1.0 at d=64
    const uint4 zero4   = make_uint4(0u, 0u, 0u, 0u);

    for (int it = 0; it < 16; it++) {
        const int nbase = chunk * 512 + it * 32;
        __syncthreads();
        // stage Kf tiles [32 n][256 m] verbatim (1024 uint4 per array)
        for (int i = tid; i < 1024; i += 256) {
            int nn = i >> 5, mc = i & 31;
            size_t src = ((size_t)bh * NN + nbase + nn) * MM + mc * 8;
            *reinterpret_cast<uint4*>(KsH + nn * 528 + mc * 16) =
                *reinterpret_cast<const uint4*>(KfH + src);
            *reinterpret_cast<uint4*>(KsL + nn * 528 + mc * 16) =
                *reinterpret_cast<const uint4*>(KfL + src);
        }
        // stage V tiles [32 n][72 d] (cols 64..71: ones/zeros)
        for (int i = tid; i < 288; i += 256) {
            int nn = i / 9, dc = i % 9;
            if (dc < 8) {
                size_t src = ((size_t)(b * NN) + nbase + nn) * 1024 + h * 64 + dc * 8;
                *reinterpret_cast<uint4*>(VsH + nn * 176 + dc * 16) =
                    *reinterpret_cast<const uint4*>(Vh + src);
                *reinterpret_cast<uint4*>(VsL + nn * 176 + dc * 16) =
                    *reinterpret_cast<const uint4*>(Vl + src);
            } else {
                *reinterpret_cast<uint4*>(VsH + nn * 176 + 128) = ones_hi;
                *reinterpret_cast<uint4*>(VsL + nn * 176 + 128) = zero4;
            }
        }
        __syncthreads();

#pragma unroll
        for (int kko = 0; kko < 32; kko += 16) {
            // A fragments (Kf^T) via x4.trans on [k=n][m] storage
            const int jj = lane >> 3, rr = lane & 7;
            const int krow = kko + rr + (jj >> 1) * 8;
            uint32_t ah[4][4], al[4][4];
#pragma unroll
            for (int mt = 0; mt < 4; mt++) {
                int mcol = wm + mt * 16 + (jj & 1) * 8;
                ldsm_x4_t(ah[mt], smaddr(KsH + krow * 528 + mcol * 2));
                ldsm_x4_t(al[mt], smaddr(KsL + krow * 528 + mcol * 2));
            }
            // B fragments (V) via x4.trans on [k=n][d] storage
            uint32_t bhf[5][2], blf[5][2], tmp[4];
#pragma unroll
            for (int pp = 0; pp < 2; pp++) {
                int dcol  = dbase + pp * 16 + ((lane >> 4) ? 8 : 0);
                int krowb = kko + rr + ((jj & 1) ? 8 : 0);
                ldsm_x4_t(tmp, smaddr(VsH + krowb * 176 + dcol * 2));
                bhf[pp*2][0] = tmp[0]; bhf[pp*2][1] = tmp[1];
                bhf[pp*2+1][0] = tmp[2]; bhf[pp*2+1][1] = tmp[3];
                ldsm_x4_t(tmp, smaddr(VsL + krowb * 176 + dcol * 2));
                blf[pp*2][0] = tmp[0]; blf[pp*2][1] = tmp[1];
                blf[pp*2+1][0] = tmp[2]; blf[pp*2+1][1] = tmp[3];
            }
            if (dgrp) {   // 5th ntile: d 64..71 (ones column lives at 64)
                int krow2 = kko + (lane & 7) + ((lane & 8) ? 8 : 0);
                ldsm_x2_t(tmp, smaddr(VsH + krow2 * 176 + 64 * 2));
                bhf[4][0] = tmp[0]; bhf[4][1] = tmp[1];
                ldsm_x2_t(tmp, smaddr(VsL + krow2 * 176 + 64 * 2));
                blf[4][0] = tmp[0]; blf[4][1] = tmp[1];
            }
#pragma unroll
            for (int mt = 0; mt < 4; mt++)
                for (int nt = 0; nt < NT; nt++) {
                    mma_bf16(acc[mt][nt], ah[mt], bhf[nt]);
                    mma_bf16(acc[mt][nt], ah[mt], blf[nt]);
                    mma_bf16(acc[mt][nt], al[mt], bhf[nt]);
                }
        }
    }

    float* Sp = Spart + ((size_t)chunk * BH + bh) * (MM * 64);
    float* Kp = Kpart + ((size_t)chunk * BH + bh) * MM;
    const int g = lane >> 2, q = lane & 3;
#pragma unroll
    for (int mt = 0; mt < 4; mt++) {
        int m = wm + mt * 16 + g;
        for (int nt = 0; nt < NT; nt++) {
            int d = dbase + nt * 8 + q * 2;
            if (d < 64) {
                *reinterpret_cast<float2*>(Sp + m * 64 + d) =
                    make_float2(acc[mt][nt][0], acc[mt][nt][1]);
                *reinterpret_cast<float2*>(Sp + (m + 8) * 64 + d) =
                    make_float2(acc[mt][nt][2], acc[mt][nt][3]);
            } else if (d == 64) {
                Kp[m]     = acc[mt][nt][0];
                Kp[m + 8] = acc[mt][nt][2];
            }
        }
    }
}

// ===========================================================================
// reduce2: sum 8 split-K partials, write S^T [bh][72][256] bf16 hi/lo
// (row 64 = Ksum, rows 65..71 zero)
// ===========================================================================
__global__ __launch_bounds__(256) void reduce2(
    const float* __restrict__ Spart, const float* __restrict__ Kpart,
    __nv_bfloat16* __restrict__ StH, __nv_bfloat16* __restrict__ StL)
{
    int i = blockIdx.x * 256 + threadIdx.x;   // BH*MM*72
    if (i >= BH * MM * 72) return;
    int bh = i / (MM * 72);
    int r  = i % (MM * 72);
    int m  = r / 72;
    int dd = r % 72;
    float s = 0.f;
    if (dd < 64) {
#pragma unroll
        for (int c = 0; c < 8; c++)
            s += Spart[((size_t)c * BH + bh) * (MM * 64) + m * 64 + dd];
    } else if (dd == 64) {
#pragma unroll
        for (int c = 0; c < 8; c++)
            s += Kpart[((size_t)c * BH + bh) * MM + m];
    }
    __nv_bfloat16 hh = __float2bfloat16(s);
    size_t o = ((size_t)bh * 72 + dd) * MM + m;
    StH[o] = hh;
    StL[o] = __float2bfloat16(s - __bfloat162float(hh));
}

// ===========================================================================
// ctx_kernel_mma: ctx[n][d] = (Qf @ S) / (Qf . Ksum + eps) * valid, bf16x3.
// A = Qf [n][m] natural; B = St [d][m]; den = output column d=64.
// 8 warps: 4 n-groups (32) x 2 d-groups (32 / 40 incl. den col).
// ===========================================================================
__global__ __launch_bounds__(256) void ctx_kernel_mma(
    const __nv_bfloat16* __restrict__ QfH, const __nv_bfloat16* __restrict__ QfL,
    const __nv_bfloat16* __restrict__ StH, const __nv_bfloat16* __restrict__ StL,
    const float* __restrict__ valid,
    __nv_bfloat16* __restrict__ ch, __nv_bfloat16* __restrict__ cl)
{
    __shared__ __align__(16) uint8_t QsH[128 * 80];
    __shared__ __align__(16) uint8_t QsL[128 * 80];
    __shared__ __align__(16) uint8_t SsH[72 * 80];
    __shared__ __align__(16) uint8_t SsL[72 * 80];
    __shared__ float denS[128];
    __shared__ float validS[128];

    const int bh = blockIdx.y;
    const int b = bh >> 4, h = bh & 15;
    const int n0 = blockIdx.x * 128;
    const int tid = threadIdx.x;
    const int lane = tid & 31;
    const int w = tid >> 5;
    const int wnb = (w >> 1) * 32;
    const int dgrp = w & 1;
    const int dbase = dgrp ? 32 : 0;
    const int NT = dgrp ? 5 : 4;

    if (tid < 128) validS[tid] = valid[b * NN + n0 + tid];

    float acc[2][5][4];
#pragma unroll
    for (int mt = 0; mt < 2; mt++)
#pragma unroll
        for (int nt = 0; nt < 5; nt++)
#pragma unroll
            for (int e = 0; e < 4; e++) acc[mt][nt][e] = 0.f;

    for (int m0 = 0; m0 < 256; m0 += 32) {
        __syncthreads();
        // stage Q tile [128 n][32 m]
        for (int i = tid; i < 512; i += 256) {
            int nn = i >> 2, mc = i & 3;
            size_t src = ((size_t)bh * NN + n0 + nn) * MM + m0 + mc * 8;
            *reinterpret_cast<uint4*>(QsH + nn * 80 + mc * 16) =
                *reinterpret_cast<const uint4*>(QfH + src);
            *reinterpret_cast<uint4*>(QsL + nn * 80 + mc * 16) =
                *reinterpret_cast<const uint4*>(QfL + src);
        }
        // stage St slice [72 d][32 m]
        for (int i = tid; i < 288; i += 256) {
            int dd = i >> 2, mc = i & 3;
            size_t src = ((size_t)bh * 72 + dd) * MM + m0 + mc * 8;
            *reinterpret_cast<uint4*>(SsH + dd * 80 + mc * 16) =
                *reinterpret_cast<const uint4*>(StH + src);
            *reinterpret_cast<uint4*>(SsL + dd * 80 + mc * 16) =
                *reinterpret_cast<const uint4*>(StL + src);
        }
        __syncthreads();

#pragma unroll
        for (int kko = 0; kko < 32; kko += 16) {
            const int jj = lane >> 3, rr = lane & 7;
            uint32_t ah[2][4], al[2][4];
#pragma unroll
            for (int mt = 0; mt < 2; mt++) {
                int nrow = wnb + mt * 16 + (jj & 1) * 8 + rr;
                int kc = kko + (jj >> 1) * 8;
                ldsm_x4(ah[mt], smaddr(QsH + nrow * 80 + kc * 2));
                ldsm_x4(al[mt], smaddr(QsL + nrow * 80 + kc * 2));
            }
            uint32_t bhf[5][2], blf[5][2], tmp[4];
#pragma unroll
            for (int pp = 0; pp < 2; pp++) {
                int drow = dbase + pp * 16 + (jj >> 1) * 8 + rr;
                int kc = kko + (jj & 1) * 8;
                ldsm_x4(tmp, smaddr(SsH + drow * 80 + kc * 2));
                bhf[pp*2][0] = tmp[0]; bhf[pp*2][1] = tmp[1];
                bhf[pp*2+1][0] = tmp[2]; bhf[pp*2+1][1] = tmp[3];
                ldsm_x4(tmp, smaddr(SsL + drow * 80 + kc * 2));
                blf[pp*2][0] = tmp[0]; blf[pp*2][1] = tmp[1];
                blf[pp*2+1][0] = tmp[2]; blf[pp*2+1][1] = tmp[3];
            }
            if (dgrp) {   // ntile 4: d 64..71 (den col at 64)
                int drow = 64 + (lane & 7);
                int kc = kko + ((lane & 8) ? 8 : 0);
                ldsm_x2(tmp, smaddr(SsH + drow * 80 + kc * 2));
                bhf[4][0] = tmp[0]; bhf[4][1] = tmp[1];
                ldsm_x2(tmp, smaddr(SsL + drow * 80 + kc * 2));
                blf[4][0] = tmp[0]; blf[4][1] = tmp[1];
            }
#pragma unroll
            for (int mt = 0; mt < 2; mt++)
                for (int nt = 0; nt < NT; nt++) {
                    mma_bf16(acc[mt][nt], ah[mt], bhf[nt]);
                    mma_bf16(acc[mt][nt], ah[mt], blf[nt]);
                    mma_bf16(acc[mt][nt], al[mt], bhf[nt]);
                }
        }
    }

    const int g = lane >> 2, q = lane & 3;
    // publish denominators (held by dgrp warps, ntile 4, q==0)
    if (dgrp && q == 0) {
#pragma unroll
        for (int mt = 0; mt < 2; mt++) {
            int n = wnb + mt * 16 + g;
            denS[n]     = acc[mt][4][0];
            denS[n + 8] = acc[mt][4][2];
        }
    }
    __syncthreads();

#pragma unroll
    for (int mt = 0; mt < 2; mt++) {
        int n = wnb + mt * 16 + g;
        float sc0 = validS[n]     / (denS[n]     + EPS_DENOM);
        float sc2 = validS[n + 8] / (denS[n + 8] + EPS_DENOM);
        size_t r0 = ((size_t)(b * NN) + n0 + n) * 1024 + h * 64;
        size_t r2 = r0 + 8 * 1024;
#pragma unroll
        for (int nt = 0; nt < 4; nt++) {
            int d = dbase + nt * 8 + q * 2;
            float v0 = acc[mt][nt][0] * sc0, v1 = acc[mt][nt][1] * sc0;
            float v2 = acc[mt][nt][2] * sc2, v3 = acc[mt][nt][3] * sc2;
            __nv_bfloat162 hh0, ll0, hh2, ll2;
            hh0.x = __float2bfloat16(v0); hh0.y = __float2bfloat16(v1);
            ll0.x = __float2bfloat16(v0 - __bfloat162float(hh0.x));
            ll0.y = __float2bfloat16(v1 - __bfloat162float(hh0.y));
            hh2.x = __float2bfloat16(v2); hh2.y = __float2bfloat16(v3);
            ll2.x = __float2bfloat16(v2 - __bfloat162float(hh2.x));
            ll2.y = __float2bfloat16(v3 - __bfloat162float(hh2.y));
            *reinterpret_cast<__nv_bfloat162*>(ch + r0 + d) = hh0;
            *reinterpret_cast<__nv_bfloat162*>(cl + r0 + d) = ll0;
            *reinterpret_cast<__nv_bfloat162*>(ch + r2 + d) = hh2;
            *reinterpret_cast<__nv_bfloat162*>(cl + r2 + d) = ll2;
        }
    }
}

// ===========================================================================
extern "C" void kernel_launch(void* const* d_in, const int* in_sizes, int n_in,
                              void* d_out, int out_size)
{
    const float* x     = (const float*)d_in[0];
    const float* Wqkv  = (const float*)d_in[1];
    const float* bqkv  = (const float*)d_in[2];
    const float* Wout  = (const float*)d_in[3];
    const float* bout  = (const float*)d_in[4];
    const float* omega = (const float*)d_in[5];
    const void*  maskp = d_in[6];
    float* out = (float*)d_out;

    float *qkv, *Spart, *Kpart, *valid;
    __nv_bfloat16 *QfH, *QfL, *KfH, *KfL, *StH, *StL;
    __nv_bfloat16 *xh, *xl, *Wqh, *Wql, *Woh, *Wol, *Vh, *Vl, *ch, *cl;
    cudaGetSymbolAddress((void**)&qkv,   g_qkv);
    cudaGetSymbolAddress((void**)&QfH,   g_QfH);
    cudaGetSymbolAddress((void**)&QfL,   g_QfL);
    cudaGetSymbolAddress((void**)&KfH,   g_KfH);
    cudaGetSymbolAddress((void**)&KfL,   g_KfL);
    cudaGetSymbolAddress((void**)&Spart, g_Spart);
    cudaGetSymbolAddress((void**)&Kpart, g_Kpart);
    cudaGetSymbolAddress((void**)&StH,   g_StH);
    cudaGetSymbolAddress((void**)&StL,   g_StL);
    cudaGetSymbolAddress((void**)&valid, g_valid);
    cudaGetSymbolAddress((void**)&xh,  g_xh);
    cudaGetSymbolAddress((void**)&xl,  g_xl);
    cudaGetSymbolAddress((void**)&Wqh, g_Wqh);
    cudaGetSymbolAddress((void**)&Wql, g_Wql);
    cudaGetSymbolAddress((void**)&Woh, g_Woh);
    cudaGetSymbolAddress((void**)&Wol, g_Wol);
    cudaGetSymbolAddress((void**)&Vh,  g_Vh);
    cudaGetSymbolAddress((void**)&Vl,  g_Vl);
    cudaGetSymbolAddress((void**)&ch,  g_ch);
    cudaGetSymbolAddress((void**)&cl,  g_cl);

    // 0) mask + operand splits
    mask_detect_kernel<<<1, 256>>>((const unsigned int*)maskp);
    mask_expand_kernel<<<BN / 256, 256>>>(maskp, valid);
    convert_split_kernel<<<(BN * DD) / 256, 256>>>(x, xh, xl, BN * DD);
    convert_split_kernel<<<(D3 * DD) / 256, 256>>>(Wqkv, Wqh, Wql, D3 * DD);
    convert_split_kernel<<<(DD * DD) / 256, 256>>>(Wout, Woh, Wol, DD * DD);

    // 1) qkv = x @ Wqkv^T + bqkv   (tensor cores, bf16x3)
    gemm_bf16x3_nt<<<dim3(D3 / 128, BN / 128), 256>>>(xh, xl, Wqh, Wql, bqkv, qkv, D3, DD);

    // 1b) split V part of qkv to bf16 hi/lo
    convert_v_kernel<<<(BN * DD) / 256, 256>>>(qkv, Vh, Vl);

    // 2) phi -> Qf/Kf bf16 hi/lo
    phi_kernel<<<dim3(NN / 64, BH, 2), 256>>>(qkv, omega, valid, QfH, QfL, KfH, KfL);

    // 3) S = Kf^T [V | 1]  (tensor cores, split-K + deterministic reduce)
    s_kernel_mma<<<dim3(8, BH), 256>>>(KfH, KfL, Vh, Vl, Spart, Kpart);
    reduce2<<<(BH * MM * 72 + 255) / 256, 256>>>(Spart, Kpart, StH, StL);

    // 4) ctx = (Qf @ [S | Ksum]) scaled  (tensor cores) -> bf16 hi/lo
    ctx_kernel_mma<<<dim3(NN / 128, BH), 256>>>(QfH, QfL, StH, StL, valid, ch, cl);

    // 5) out = ctx @ Wout^T + bout (tensor cores, bf16x3)
    gemm_bf16x3_nt<<<dim3(DD / 128, BN / 128), 256>>>(ch, cl, Woh, Wol, bout, out, DD, DD);
}

// round 8
// speedup vs baseline: 2.0792x; 1.0854x over previous
#include <cuda_runtime.h>
#include <cuda_bf16.h>
#include <math.h>
#include <stdint.h>

//  B=4, N=4096, D=1024, H=16, M=256, dk=64
#define BB   4
#define NN   4096
#define DD   1024
#define HH   16
#define MM   256
#define DKK  64
#define BN   (BB*NN)          // 16384
#define BH   (BB*HH)          // 64
#define D3   (3*DD)           // 3072
#define NCHUNK 16

#define INV_SQRT_M 0.0625f
#define EPS_DENOM  1e-6f

// ---------------- device scratch (no allocations allowed) -----------------
__device__ float g_qkv[(size_t)BN * D3];                 // 201 MB
__device__ __nv_bfloat16 g_QfH[(size_t)BH * NN * MM];    // 134 MB total Qf/Kf
__device__ __nv_bfloat16 g_QfL[(size_t)BH * NN * MM];
__device__ __nv_bfloat16 g_KfH[(size_t)BH * NN * MM];
__device__ __nv_bfloat16 g_KfL[(size_t)BH * NN * MM];
__device__ float g_Spart[(size_t)NCHUNK * BH * MM * 64]; // 67 MB
__device__ float g_Kpart[(size_t)NCHUNK * BH * MM];
__device__ __nv_bfloat16 g_StH[(size_t)BH * 72 * MM];    // S^T + Ksum row
__device__ __nv_bfloat16 g_StL[(size_t)BH * 72 * MM];
__device__ float g_valid[(size_t)BN];
__device__ int   g_mask_mode;
__device__ __nv_bfloat16 g_xh[(size_t)BN * DD];
__device__ __nv_bfloat16 g_xl[(size_t)BN * DD];
__device__ __nv_bfloat16 g_Wqh[(size_t)D3 * DD];
__device__ __nv_bfloat16 g_Wql[(size_t)D3 * DD];
__device__ __nv_bfloat16 g_Woh[(size_t)DD * DD];
__device__ __nv_bfloat16 g_Wol[(size_t)DD * DD];
__device__ __nv_bfloat16 g_Vh[(size_t)BN * DD];
__device__ __nv_bfloat16 g_Vl[(size_t)BN * DD];
__device__ __nv_bfloat16 g_ch[(size_t)BN * DD];
__device__ __nv_bfloat16 g_cl[(size_t)BN * DD];

// ---------------- ldmatrix / mma helpers -----------------------------------
__device__ __forceinline__ uint32_t smaddr(const void* p) {
    return (uint32_t)__cvta_generic_to_shared(p);
}
__device__ __forceinline__ void ldsm_x4(uint32_t* r, uint32_t a) {
    asm volatile("ldmatrix.sync.aligned.m8n8.x4.shared.b16 {%0,%1,%2,%3}, [%4];"
        : "=r"(r[0]), "=r"(r[1]), "=r"(r[2]), "=r"(r[3]) : "r"(a));
}
__device__ __forceinline__ void ldsm_x4_t(uint32_t* r, uint32_t a) {
    asm volatile("ldmatrix.sync.aligned.m8n8.x4.trans.shared.b16 {%0,%1,%2,%3}, [%4];"
        : "=r"(r[0]), "=r"(r[1]), "=r"(r[2]), "=r"(r[3]) : "r"(a));
}
__device__ __forceinline__ void ldsm_x2(uint32_t* r, uint32_t a) {
    asm volatile("ldmatrix.sync.aligned.m8n8.x2.shared.b16 {%0,%1}, [%2];"
        : "=r"(r[0]), "=r"(r[1]) : "r"(a));
}
__device__ __forceinline__ void ldsm_x2_t(uint32_t* r, uint32_t a) {
    asm volatile("ldmatrix.sync.aligned.m8n8.x2.trans.shared.b16 {%0,%1}, [%2];"
        : "=r"(r[0]), "=r"(r[1]) : "r"(a));
}
__device__ __forceinline__ void mma_bf16(float* d, const uint32_t* a, const uint32_t* b)
{
    asm volatile(
        "mma.sync.aligned.m16n8k16.row.col.f32.bf16.bf16.f32 "
        "{%0,%1,%2,%3},{%4,%5,%6,%7},{%8,%9},{%0,%1,%2,%3};"
        : "+f"(d[0]), "+f"(d[1]), "+f"(d[2]), "+f"(d[3])
        : "r"(a[0]), "r"(a[1]), "r"(a[2]), "r"(a[3]), "r"(b[0]), "r"(b[1]));
}

// ===========================================================================
// Mask dtype detection + expansion (int32 / float32 / uint8 robust)
// ===========================================================================
__global__ void mask_detect_kernel(const unsigned int* __restrict__ mw)
{
    __shared__ int sawF, sawB;
    if (threadIdx.x == 0) { sawF = 0; sawB = 0; }
    __syncthreads();
    for (int i = threadIdx.x; i < 4096; i += 256) {
        unsigned int v = mw[i];
        if (v == 0x3F800000u) atomicOr(&sawF, 1);
        else if (v != 0u && v != 1u) atomicOr(&sawB, 1);
    }
    __syncthreads();
    if (threadIdx.x == 0) g_mask_mode = sawF ? 1 : (sawB ? 2 : 0);
}

__global__ void mask_expand_kernel(const void* __restrict__ m, float* __restrict__ valid)
{
    int i = blockIdx.x * 256 + threadIdx.x;
    if (i >= BN) return;
    int mode = g_mask_mode;
    bool pad;
    if (mode == 0)      pad = ((const int*)m)[i] != 0;
    else if (mode == 1) pad = ((const float*)m)[i] != 0.0f;
    else                pad = ((const unsigned char*)m)[i] != 0;
    valid[i] = pad ? 0.0f : 1.0f;
}

// fp32 -> (hi, lo) bf16 split (contiguous)
__global__ void convert_split_kernel(const float* __restrict__ src,
                                     __nv_bfloat16* __restrict__ hi,
                                     __nv_bfloat16* __restrict__ lo, int n)
{
    int i = blockIdx.x * 256 + threadIdx.x;
    if (i >= n) return;
    float v = src[i];
    __nv_bfloat16 h = __float2bfloat16(v);
    hi[i] = h;
    lo[i] = __float2bfloat16(v - __bfloat162float(h));
}

// split V out of qkv (columns 2048..3071) into [BN][1024] bf16 hi/lo
__global__ void convert_v_kernel(const float* __restrict__ qkv,
                                 __nv_bfloat16* __restrict__ Vh,
                                 __nv_bfloat16* __restrict__ Vl)
{
    int i = blockIdx.x * 256 + threadIdx.x;   // 0 .. BN*1024
    int row = i >> 10, col = i & 1023;
    float v = qkv[(size_t)row * D3 + 2 * DD + col];
    __nv_bfloat16 h = __float2bfloat16(v);
    Vh[i] = h;
    Vl[i] = __float2bfloat16(v - __bfloat162float(h));
}

// ===========================================================================
// bf16x3 tensor-core GEMM, ldmatrix mainloop.
// C = A(MxK)*Bt(NxK)^T + bias. Block 128x128, BK=32, 8 warps (64x32 each).
// Row stride 40 bf16 (80B): ldmatrix conflict-free (r*20 mod 32 distinct).
// ===========================================================================
__global__ __launch_bounds__(256, 2) void gemm_bf16x3_nt(
    const __nv_bfloat16* __restrict__ Ahi, const __nv_bfloat16* __restrict__ Alo,
    const __nv_bfloat16* __restrict__ Bhi, const __nv_bfloat16* __restrict__ Blo,
    const float* __restrict__ bias, float* __restrict__ C,
    int Nd, int Kd)
{
    __shared__ uint32_t As_h[128][20];
    __shared__ uint32_t As_l[128][20];
    __shared__ uint32_t Bs_h[128][20];
    __shared__ uint32_t Bs_l[128][20];

    const int tid  = threadIdx.x;
    const int lane = tid & 31;
    const int w    = tid >> 5;
    const int wm   = (w >> 2) * 64;
    const int wn   = (w & 3) * 32;
    const int q    = lane & 3;
    const int g    = lane >> 2;
    const int jj   = lane >> 3;
    const int rr   = lane & 7;
    const int rowBase = blockIdx.y * 128;
    const int colBase = blockIdx.x * 128;

    float acc[4][4][4];
#pragma unroll
    for (int mt = 0; mt < 4; mt++)
#pragma unroll
        for (int nt = 0; nt < 4; nt++)
#pragma unroll
            for (int e = 0; e < 4; e++) acc[mt][nt][e] = 0.f;

    for (int k0 = 0; k0 < Kd; k0 += 32) {
#pragma unroll
        for (int t = 0; t < 2; t++) {
            int v  = tid + t * 256;
            int r  = v >> 2;
            int ch = v & 3;
            size_t ga = (size_t)(rowBase + r) * Kd + k0 + ch * 8;
            size_t gb = (size_t)(colBase + r) * Kd + k0 + ch * 8;
            *reinterpret_cast<uint4*>(&As_h[r][ch * 4]) = *reinterpret_cast<const uint4*>(Ahi + ga);
            *reinterpret_cast<uint4*>(&As_l[r][ch * 4]) = *reinterpret_cast<const uint4*>(Alo + ga);
            *reinterpret_cast<uint4*>(&Bs_h[r][ch * 4]) = *reinterpret_cast<const uint4*>(Bhi + gb);
            *reinterpret_cast<uint4*>(&Bs_l[r][ch * 4]) = *reinterpret_cast<const uint4*>(Blo + gb);
        }
        __syncthreads();

#pragma unroll
        for (int kko = 0; kko < 32; kko += 16) {
            // B fragments (n8k16) via non-trans ldmatrix on [n][k] rows
            uint32_t bhf[4][2], blf[4][2], tmp[4];
#pragma unroll
            for (int pp = 0; pp < 2; pp++) {
                int nrow = wn + pp * 16 + (jj >> 1) * 8 + rr;
                int kc = kko + (jj & 1) * 8;
                ldsm_x4(tmp, smaddr(reinterpret_cast<const uint8_t*>(Bs_h) + nrow * 80 + kc * 2));
                bhf[pp*2][0] = tmp[0]; bhf[pp*2][1] = tmp[1];
                bhf[pp*2+1][0] = tmp[2]; bhf[pp*2+1][1] = tmp[3];
                ldsm_x4(tmp, smaddr(reinterpret_cast<const uint8_t*>(Bs_l) + nrow * 80 + kc * 2));
                blf[pp*2][0] = tmp[0]; blf[pp*2][1] = tmp[1];
                blf[pp*2+1][0] = tmp[2]; blf[pp*2+1][1] = tmp[3];
            }
#pragma unroll
            for (int mt = 0; mt < 4; mt++) {
                int arow = wm + mt * 16 + (jj & 1) * 8 + rr;
                int kc = kko + (jj >> 1) * 8;
                uint32_t ah[4], al[4];
                ldsm_x4(ah, smaddr(reinterpret_cast<const uint8_t*>(As_h) + arow * 80 + kc * 2));
                ldsm_x4(al, smaddr(reinterpret_cast<const uint8_t*>(As_l) + arow * 80 + kc * 2));
#pragma unroll
                for (int nt = 0; nt < 4; nt++) {
                    mma_bf16(acc[mt][nt], ah, bhf[nt]);
                    mma_bf16(acc[mt][nt], ah, blf[nt]);
                    mma_bf16(acc[mt][nt], al, bhf[nt]);
                }
            }
        }
        __syncthreads();
    }

#pragma unroll
    for (int mt = 0; mt < 4; mt++) {
        int r0 = rowBase + wm + mt * 16 + g;
#pragma unroll
        for (int nt = 0; nt < 4; nt++) {
            int c = colBase + wn + nt * 8 + q * 2;
            float b0 = bias[c], b1 = bias[c + 1];
            float2* p0 = reinterpret_cast<float2*>(C + (size_t)r0 * Nd + c);
            float2* p1 = reinterpret_cast<float2*>(C + (size_t)(r0 + 8) * Nd + c);
            *p0 = make_float2(acc[mt][nt][0] + b0, acc[mt][nt][1] + b1);
            *p1 = make_float2(acc[mt][nt][2] + b0, acc[mt][nt][3] + b1);
        }
    }
}

// ===========================================================================
// phi kernel: writes Qf/Kf as bf16 hi/lo arrays.  __expf (ex2.approx).
// ===========================================================================
__global__ __launch_bounds__(256) void phi_kernel(
    const float* __restrict__ qkv, const float* __restrict__ omega,
    const float* __restrict__ valid,
    __nv_bfloat16* __restrict__ QfH, __nv_bfloat16* __restrict__ QfL,
    __nv_bfloat16* __restrict__ KfH, __nv_bfloat16* __restrict__ KfL)
{
    const int ntile = blockIdx.x;
    const int bh    = blockIdx.y;
    const int isK   = blockIdx.z;
    const int b = bh >> 4, h = bh & 15;
    const int n0 = ntile * 64;
    const int tid = threadIdx.x;
    const int ty = tid >> 4, tx = tid & 15;

    __shared__ float Ts[16][68];
    __shared__ float Om[16][257];
    __shared__ float validS[64];

    if (tid < 64)
        validS[tid] = valid[b * NN + n0 + tid];

    const float* src = qkv + ((size_t)(b * NN + n0)) * D3 + (size_t)isK * DD + h * DKK;
    const float* om  = omega + (size_t)h * MM * DKK;

    float acc[4][16];
    float sq[4];
#pragma unroll
    for (int i = 0; i < 4; i++) {
        sq[i] = 0.f;
#pragma unroll
        for (int j = 0; j < 16; j++) acc[i][j] = 0.f;
    }

    for (int kc = 0; kc < 4; kc++) {
        __syncthreads();
        for (int i = tid; i < 64 * 16; i += 256) {
            int r = i >> 4, kk = i & 15;
            float v = src[(size_t)r * D3 + kc * 16 + kk];
            if (!isK) v *= validS[r];
            Ts[kk][r] = v;
        }
        for (int i = tid; i < 256 * 16; i += 256) {
            int m = i >> 4, kk = i & 15;
            Om[kk][m] = om[(size_t)m * DKK + kc * 16 + kk];
        }
        __syncthreads();
#pragma unroll
        for (int k = 0; k < 16; k++) {
            float a[4];
#pragma unroll
            for (int i = 0; i < 4; i++) {
                a[i] = Ts[k][ty + i * 16];
                sq[i] += a[i] * a[i];
            }
#pragma unroll
            for (int j = 0; j < 16; j++) {
                float bx = Om[k][tx + j * 16];
#pragma unroll
                for (int i = 0; i < 4; i++) acc[i][j] += a[i] * bx;
            }
        }
    }

    float base[4];
#pragma unroll
    for (int i = 0; i < 4; i++) {
        float mx = acc[i][0];
#pragma unroll
        for (int j = 1; j < 16; j++) mx = fmaxf(mx, acc[i][j]);
#pragma unroll
        for (int s = 1; s < 16; s <<= 1)
            mx = fmaxf(mx, __shfl_xor_sync(0xffffffffu, mx, s));
        base[i] = -mx - 0.5f * sq[i];
    }

    size_t off = ((size_t)bh * NN + n0) * MM;
    __nv_bfloat16* dh = (isK ? KfH : QfH) + off;
    __nv_bfloat16* dl = (isK ? KfL : QfL) + off;
#pragma unroll
    for (int i = 0; i < 4; i++) {
        int r = ty + i * 16;
        float post = isK ? (INV_SQRT_M * validS[r]) : INV_SQRT_M;
#pragma unroll
        for (int j = 0; j < 16; j++) {
            float v = __expf(acc[i][j] + base[i]) * post;
            __nv_bfloat16 hh = __float2bfloat16(v);
            size_t idx = (size_t)r * MM + tx + j * 16;
            dh[idx] = hh;
            dl[idx] = __float2bfloat16(v - __bfloat162float(hh));
        }
    }
}

// ===========================================================================
// s_kernel_mma: per (chunk of 256 n, bh): Spart[m<256][d<64] = Kf^T V, with a
// ones-column at d=64 producing Kpart. bf16x3 via mma + ldmatrix.trans.
// ===========================================================================
__global__ __launch_bounds__(256) void s_kernel_mma(
    const __nv_bfloat16* __restrict__ KfH, const __nv_bfloat16* __restrict__ KfL,
    const __nv_bfloat16* __restrict__ Vh,  const __nv_bfloat16* __restrict__ Vl,
    float* __restrict__ Spart, float* __restrict__ Kpart)
{
    __shared__ __align__(16) uint8_t KsH[32 * 528];
    __shared__ __align__(16) uint8_t KsL[32 * 528];
    __shared__ __align__(16) uint8_t VsH[32 * 176];
    __shared__ __align__(16) uint8_t VsL[32 * 176];

    const int chunk = blockIdx.x;     // 0..NCHUNK-1
    const int bh    = blockIdx.y;     // 0..63
    const int b = bh >> 4, h = bh & 15;
    const int tid = threadIdx.x;
    const int lane = tid & 31;
    const int w = tid >> 5;
    const int wm = (w >> 1) * 64;
    const int dgrp = w & 1;
    const int dbase = dgrp ? 32 : 0;
    const int NT = dgrp ? 5 : 4;

    float acc[4][5][4];
#pragma unroll
    for (int mt = 0; mt < 4; mt++)
#pragma unroll
        for (int nt = 0; nt < 5; nt++)
#pragma unroll
            for (int e = 0; e < 4; e++) acc[mt][nt][e] = 0.f;

    const uint4 ones_hi = make_uint4(0x00003F80u, 0u, 0u, 0u);  // bf16 1.0 at d=64
    const uint4 zero4   = make_uint4(0u, 0u, 0u, 0u);

    for (int it = 0; it < NN / NCHUNK / 32; it++) {
        const int nbase = chunk * (NN / NCHUNK) + it * 32;
        __syncthreads();
        for (int i = tid; i < 1024; i += 256) {
            int nn = i >> 5, mc = i & 31;
            size_t src = ((size_t)bh * NN + nbase + nn) * MM + mc * 8;
            *reinterpret_cast<uint4*>(KsH + nn * 528 + mc * 16) =
                *reinterpret_cast<const uint4*>(KfH + src);
            *reinterpret_cast<uint4*>(KsL + nn * 528 + mc * 16) =
                *reinterpret_cast<const uint4*>(KfL + src);
        }
        for (int i = tid; i < 288; i += 256) {
            int nn = i / 9, dc = i % 9;
            if (dc < 8) {
                size_t src = ((size_t)(b * NN) + nbase + nn) * 1024 + h * 64 + dc * 8;
                *reinterpret_cast<uint4*>(VsH + nn * 176 + dc * 16) =
                    *reinterpret_cast<const uint4*>(Vh + src);
                *reinterpret_cast<uint4*>(VsL + nn * 176 + dc * 16) =
                    *reinterpret_cast<const uint4*>(Vl + src);
            } else {
                *reinterpret_cast<uint4*>(VsH + nn * 176 + 128) = ones_hi;
                *reinterpret_cast<uint4*>(VsL + nn * 176 + 128) = zero4;
            }
        }
        __syncthreads();

#pragma unroll
        for (int kko = 0; kko < 32; kko += 16) {
            const int jj = lane >> 3, rr = lane & 7;
            const int krow = kko + rr + (jj >> 1) * 8;
            uint32_t ah[4][4], al[4][4];
#pragma unroll
            for (int mt = 0; mt < 4; mt++) {
                int mcol = wm + mt * 16 + (jj & 1) * 8;
                ldsm_x4_t(ah[mt], smaddr(KsH + krow * 528 + mcol * 2));
                ldsm_x4_t(al[mt], smaddr(KsL + krow * 528 + mcol * 2));
            }
            uint32_t bhf[5][2], blf[5][2], tmp[4];
#pragma unroll
            for (int pp = 0; pp < 2; pp++) {
                int dcol  = dbase + pp * 16 + ((lane >> 4) ? 8 : 0);
                int krowb = kko + rr + ((jj & 1) ? 8 : 0);
                ldsm_x4_t(tmp, smaddr(VsH + krowb * 176 + dcol * 2));
                bhf[pp*2][0] = tmp[0]; bhf[pp*2][1] = tmp[1];
                bhf[pp*2+1][0] = tmp[2]; bhf[pp*2+1][1] = tmp[3];
                ldsm_x4_t(tmp, smaddr(VsL + krowb * 176 + dcol * 2));
                blf[pp*2][0] = tmp[0]; blf[pp*2][1] = tmp[1];
                blf[pp*2+1][0] = tmp[2]; blf[pp*2+1][1] = tmp[3];
            }
            if (dgrp) {
                int krow2 = kko + (lane & 7) + ((lane & 8) ? 8 : 0);
                ldsm_x2_t(tmp, smaddr(VsH + krow2 * 176 + 64 * 2));
                bhf[4][0] = tmp[0]; bhf[4][1] = tmp[1];
                ldsm_x2_t(tmp, smaddr(VsL + krow2 * 176 + 64 * 2));
                blf[4][0] = tmp[0]; blf[4][1] = tmp[1];
            }
#pragma unroll
            for (int mt = 0; mt < 4; mt++)
                for (int nt = 0; nt < NT; nt++) {
                    mma_bf16(acc[mt][nt], ah[mt], bhf[nt]);
                    mma_bf16(acc[mt][nt], ah[mt], blf[nt]);
                    mma_bf16(acc[mt][nt], al[mt], bhf[nt]);
                }
        }
    }

    float* Sp = Spart + ((size_t)chunk * BH + bh) * (MM * 64);
    float* Kp = Kpart + ((size_t)chunk * BH + bh) * MM;
    const int g = lane >> 2, q = lane & 3;
#pragma unroll
    for (int mt = 0; mt < 4; mt++) {
        int m = wm + mt * 16 + g;
        for (int nt = 0; nt < NT; nt++) {
            int d = dbase + nt * 8 + q * 2;
            if (d < 64) {
                *reinterpret_cast<float2*>(Sp + m * 64 + d) =
                    make_float2(acc[mt][nt][0], acc[mt][nt][1]);
                *reinterpret_cast<float2*>(Sp + (m + 8) * 64 + d) =
                    make_float2(acc[mt][nt][2], acc[mt][nt][3]);
            } else if (d == 64) {
                Kp[m]     = acc[mt][nt][0];
                Kp[m + 8] = acc[mt][nt][2];
            }
        }
    }
}

// ===========================================================================
// reduce2: sum NCHUNK split-K partials, write S^T [bh][72][256] bf16 hi/lo
// ===========================================================================
__global__ __launch_bounds__(256) void reduce2(
    const float* __restrict__ Spart, const float* __restrict__ Kpart,
    __nv_bfloat16* __restrict__ StH, __nv_bfloat16* __restrict__ StL)
{
    int i = blockIdx.x * 256 + threadIdx.x;
    if (i >= BH * MM * 72) return;
    int bh = i / (MM * 72);
    int r  = i % (MM * 72);
    int m  = r / 72;
    int dd = r % 72;
    float s = 0.f;
    if (dd < 64) {
#pragma unroll
        for (int c = 0; c < NCHUNK; c++)
            s += Spart[((size_t)c * BH + bh) * (MM * 64) + m * 64 + dd];
    } else if (dd == 64) {
#pragma unroll
        for (int c = 0; c < NCHUNK; c++)
            s += Kpart[((size_t)c * BH + bh) * MM + m];
    }
    __nv_bfloat16 hh = __float2bfloat16(s);
    size_t o = ((size_t)bh * 72 + dd) * MM + m;
    StH[o] = hh;
    StL[o] = __float2bfloat16(s - __bfloat162float(hh));
}

// ===========================================================================
// ctx_kernel_mma: ctx = (Qf @ [S|Ksum]) / den * valid, bf16x3.
// ===========================================================================
__global__ __launch_bounds__(256) void ctx_kernel_mma(
    const __nv_bfloat16* __restrict__ QfH, const __nv_bfloat16* __restrict__ QfL,
    const __nv_bfloat16* __restrict__ StH, const __nv_bfloat16* __restrict__ StL,
    const float* __restrict__ valid,
    __nv_bfloat16* __restrict__ ch, __nv_bfloat16* __restrict__ cl)
{
    __shared__ __align__(16) uint8_t QsH[128 * 80];
    __shared__ __align__(16) uint8_t QsL[128 * 80];
    __shared__ __align__(16) uint8_t SsH[72 * 80];
    __shared__ __align__(16) uint8_t SsL[72 * 80];
    __shared__ float denS[128];
    __shared__ float validS[128];

    const int bh = blockIdx.y;
    const int b = bh >> 4, h = bh & 15;
    const int n0 = blockIdx.x * 128;
    const int tid = threadIdx.x;
    const int lane = tid & 31;
    const int w = tid >> 5;
    const int wnb = (w >> 1) * 32;
    const int dgrp = w & 1;
    const int dbase = dgrp ? 32 : 0;
    const int NT = dgrp ? 5 : 4;

    if (tid < 128) validS[tid] = valid[b * NN + n0 + tid];

    float acc[2][5][4];
#pragma unroll
    for (int mt = 0; mt < 2; mt++)
#pragma unroll
        for (int nt = 0; nt < 5; nt++)
#pragma unroll
            for (int e = 0; e < 4; e++) acc[mt][nt][e] = 0.f;

    for (int m0 = 0; m0 < 256; m0 += 32) {
        __syncthreads();
        for (int i = tid; i < 512; i += 256) {
            int nn = i >> 2, mc = i & 3;
            size_t src = ((size_t)bh * NN + n0 + nn) * MM + m0 + mc * 8;
            *reinterpret_cast<uint4*>(QsH + nn * 80 + mc * 16) =
                *reinterpret_cast<const uint4*>(QfH + src);
            *reinterpret_cast<uint4*>(QsL + nn * 80 + mc * 16) =
                *reinterpret_cast<const uint4*>(QfL + src);
        }
        for (int i = tid; i < 288; i += 256) {
            int dd = i >> 2, mc = i & 3;
            size_t src = ((size_t)bh * 72 + dd) * MM + m0 + mc * 8;
            *reinterpret_cast<uint4*>(SsH + dd * 80 + mc * 16) =
                *reinterpret_cast<const uint4*>(StH + src);
            *reinterpret_cast<uint4*>(SsL + dd * 80 + mc * 16) =
                *reinterpret_cast<const uint4*>(StL + src);
        }
        __syncthreads();

#pragma unroll
        for (int kko = 0; kko < 32; kko += 16) {
            const int jj = lane >> 3, rr = lane & 7;
            uint32_t ah[2][4], al[2][4];
#pragma unroll
            for (int mt = 0; mt < 2; mt++) {
                int nrow = wnb + mt * 16 + (jj & 1) * 8 + rr;
                int kc = kko + (jj >> 1) * 8;
                ldsm_x4(ah[mt], smaddr(QsH + nrow * 80 + kc * 2));
                ldsm_x4(al[mt], smaddr(QsL + nrow * 80 + kc * 2));
            }
            uint32_t bhf[5][2], blf[5][2], tmp[4];
#pragma unroll
            for (int pp = 0; pp < 2; pp++) {
                int drow = dbase + pp * 16 + (jj >> 1) * 8 + rr;
                int kc = kko + (jj & 1) * 8;
                ldsm_x4(tmp, smaddr(SsH + drow * 80 + kc * 2));
                bhf[pp*2][0] = tmp[0]; bhf[pp*2][1] = tmp[1];
                bhf[pp*2+1][0] = tmp[2]; bhf[pp*2+1][1] = tmp[3];
                ldsm_x4(tmp, smaddr(SsL + drow * 80 + kc * 2));
                blf[pp*2][0] = tmp[0]; blf[pp*2][1] = tmp[1];
                blf[pp*2+1][0] = tmp[2]; blf[pp*2+1][1] = tmp[3];
            }
            if (dgrp) {
                int drow = 64 + (lane & 7);
                int kc = kko + ((lane & 8) ? 8 : 0);
                ldsm_x2(tmp, smaddr(SsH + drow * 80 + kc * 2));
                bhf[4][0] = tmp[0]; bhf[4][1] = tmp[1];
                ldsm_x2(tmp, smaddr(SsL + drow * 80 + kc * 2));
                blf[4][0] = tmp[0]; blf[4][1] = tmp[1];
            }
#pragma unroll
            for (int mt = 0; mt < 2; mt++)
                for (int nt = 0; nt < NT; nt++) {
                    mma_bf16(acc[mt][nt], ah[mt], bhf[nt]);
                    mma_bf16(acc[mt][nt], ah[mt], blf[nt]);
                    mma_bf16(acc[mt][nt], al[mt], bhf[nt]);
                }
        }
    }

    const int g = lane >> 2, q = lane & 3;
    if (dgrp && q == 0) {
#pragma unroll
        for (int mt = 0; mt < 2; mt++) {
            int n = wnb + mt * 16 + g;
            denS[n]     = acc[mt][4][0];
            denS[n + 8] = acc[mt][4][2];
        }
    }
    __syncthreads();

#pragma unroll
    for (int mt = 0; mt < 2; mt++) {
        int n = wnb + mt * 16 + g;
        float sc0 = validS[n]     / (denS[n]     + EPS_DENOM);
        float sc2 = validS[n + 8] / (denS[n + 8] + EPS_DENOM);
        size_t r0 = ((size_t)(b * NN) + n0 + n) * 1024 + h * 64;
        size_t r2 = r0 + 8 * 1024;
#pragma unroll
        for (int nt = 0; nt < 4; nt++) {
            int d = dbase + nt * 8 + q * 2;
            float v0 = acc[mt][nt][0] * sc0, v1 = acc[mt][nt][1] * sc0;
            float v2 = acc[mt][nt][2] * sc2, v3 = acc[mt][nt][3] * sc2;
            __nv_bfloat162 hh0, ll0, hh2, ll2;
            hh0.x = __float2bfloat16(v0); hh0.y = __float2bfloat16(v1);
            ll0.x = __float2bfloat16(v0 - __bfloat162float(hh0.x));
            ll0.y = __float2bfloat16(v1 - __bfloat162float(hh0.y));
            hh2.x = __float2bfloat16(v2); hh2.y = __float2bfloat16(v3);
            ll2.x = __float2bfloat16(v2 - __bfloat162float(hh2.x));
            ll2.y = __float2bfloat16(v3 - __bfloat162float(hh2.y));
            *reinterpret_cast<__nv_bfloat162*>(ch + r0 + d) = hh0;
            *reinterpret_cast<__nv_bfloat162*>(cl + r0 + d) = ll0;
            *reinterpret_cast<__nv_bfloat162*>(ch + r2 + d) = hh2;
            *reinterpret_cast<__nv_bfloat162*>(cl + r2 + d) = ll2;
        }
    }
}

// ===========================================================================
extern "C" void kernel_launch(void* const* d_in, const int* in_sizes, int n_in,
                              void* d_out, int out_size)
{
    const float* x     = (const float*)d_in[0];
    const float* Wqkv  = (const float*)d_in[1];
    const float* bqkv  = (const float*)d_in[2];
    const float* Wout  = (const float*)d_in[3];
    const float* bout  = (const float*)d_in[4];
    const float* omega = (const float*)d_in[5];
    const void*  maskp = d_in[6];
    float* out = (float*)d_out;

    float *qkv, *Spart, *Kpart, *valid;
    __nv_bfloat16 *QfH, *QfL, *KfH, *KfL, *StH, *StL;
    __nv_bfloat16 *xh, *xl, *Wqh, *Wql, *Woh, *Wol, *Vh, *Vl, *ch, *cl;
    cudaGetSymbolAddress((void**)&qkv,   g_qkv);
    cudaGetSymbolAddress((void**)&QfH,   g_QfH);
    cudaGetSymbolAddress((void**)&QfL,   g_QfL);
    cudaGetSymbolAddress((void**)&KfH,   g_KfH);
    cudaGetSymbolAddress((void**)&KfL,   g_KfL);
    cudaGetSymbolAddress((void**)&Spart, g_Spart);
    cudaGetSymbolAddress((void**)&Kpart, g_Kpart);
    cudaGetSymbolAddress((void**)&StH,   g_StH);
    cudaGetSymbolAddress((void**)&StL,   g_StL);
    cudaGetSymbolAddress((void**)&valid, g_valid);
    cudaGetSymbolAddress((void**)&xh,  g_xh);
    cudaGetSymbolAddress((void**)&xl,  g_xl);
    cudaGetSymbolAddress((void**)&Wqh, g_Wqh);
    cudaGetSymbolAddress((void**)&Wql, g_Wql);
    cudaGetSymbolAddress((void**)&Woh, g_Woh);
    cudaGetSymbolAddress((void**)&Wol, g_Wol);
    cudaGetSymbolAddress((void**)&Vh,  g_Vh);
    cudaGetSymbolAddress((void**)&Vl,  g_Vl);
    cudaGetSymbolAddress((void**)&ch,  g_ch);
    cudaGetSymbolAddress((void**)&cl,  g_cl);

    // 0) mask + operand splits
    mask_detect_kernel<<<1, 256>>>((const unsigned int*)maskp);
    mask_expand_kernel<<<BN / 256, 256>>>(maskp, valid);
    convert_split_kernel<<<(BN * DD) / 256, 256>>>(x, xh, xl, BN * DD);
    convert_split_kernel<<<(D3 * DD) / 256, 256>>>(Wqkv, Wqh, Wql, D3 * DD);
    convert_split_kernel<<<(DD * DD) / 256, 256>>>(Wout, Woh, Wol, DD * DD);

    // 1) qkv = x @ Wqkv^T + bqkv   (tensor cores, bf16x3, ldmatrix)
    gemm_bf16x3_nt<<<dim3(D3 / 128, BN / 128), 256>>>(xh, xl, Wqh, Wql, bqkv, qkv, D3, DD);

    // 1b) split V part of qkv to bf16 hi/lo
    convert_v_kernel<<<(BN * DD) / 256, 256>>>(qkv, Vh, Vl);

    // 2) phi -> Qf/Kf bf16 hi/lo  (__expf)
    phi_kernel<<<dim3(NN / 64, BH, 2), 256>>>(qkv, omega, valid, QfH, QfL, KfH, KfL);

    // 3) S = Kf^T [V | 1]  (tensor cores, 16-way split-K + deterministic reduce)
    s_kernel_mma<<<dim3(NCHUNK, BH), 256>>>(KfH, KfL, Vh, Vl, Spart, Kpart);
    reduce2<<<(BH * MM * 72 + 255) / 256, 256>>>(Spart, Kpart, StH, StL);

    // 4) ctx = (Qf @ [S | Ksum]) scaled  (tensor cores) -> bf16 hi/lo
    ctx_kernel_mma<<<dim3(NN / 128, BH), 256>>>(QfH, QfL, StH, StL, valid, ch, cl);

    // 5) out = ctx @ Wout^T + bout (tensor cores, bf16x3, ldmatrix)
    gemm_bf16x3_nt<<<dim3(DD / 128, BN / 128), 256>>>(ch, cl, Woh, Wol, bout, out, DD, DD);
}

// round 12
// speedup vs baseline: 2.1979x; 1.0571x over previous
#include <cuda_runtime.h>
#include <cuda_bf16.h>
#include <math.h>
#include <stdint.h>

//  B=4, N=4096, D=1024, H=16, M=256, dk=64
#define BB   4
#define NN   4096
#define DD   1024
#define HH   16
#define MM   256
#define DKK  64
#define BN   (BB*NN)          // 16384
#define BH   (BB*HH)          // 64
#define D3   (3*DD)           // 3072
#define NCHUNK 16

#define INV_SQRT_M 0.0625f
#define EPS_DENOM  1e-6f

// ---------------- device scratch (no allocations allowed) -----------------
__device__ float g_qkv[(size_t)BN * D3];                 // 201 MB
__device__ __nv_bfloat16 g_QfH[(size_t)BH * NN * MM];
__device__ __nv_bfloat16 g_QfL[(size_t)BH * NN * MM];
__device__ __nv_bfloat16 g_KfH[(size_t)BH * NN * MM];
__device__ __nv_bfloat16 g_KfL[(size_t)BH * NN * MM];
__device__ float g_Spart[(size_t)NCHUNK * BH * MM * 64];
__device__ float g_Kpart[(size_t)NCHUNK * BH * MM];
__device__ __nv_bfloat16 g_StH[(size_t)BH * 72 * MM];
__device__ __nv_bfloat16 g_StL[(size_t)BH * 72 * MM];
__device__ float g_valid[(size_t)BN];
__device__ int   g_mask_mode;
__device__ __nv_bfloat16 g_xh[(size_t)BN * DD];
__device__ __nv_bfloat16 g_xl[(size_t)BN * DD];
__device__ __nv_bfloat16 g_Wqh[(size_t)D3 * DD];
__device__ __nv_bfloat16 g_Wql[(size_t)D3 * DD];
__device__ __nv_bfloat16 g_Woh[(size_t)DD * DD];
__device__ __nv_bfloat16 g_Wol[(size_t)DD * DD];
__device__ __nv_bfloat16 g_omh[(size_t)HH * MM * DKK];
__device__ __nv_bfloat16 g_oml[(size_t)HH * MM * DKK];
__device__ __nv_bfloat16 g_Vh[(size_t)BN * DD];
__device__ __nv_bfloat16 g_Vl[(size_t)BN * DD];
__device__ __nv_bfloat16 g_ch[(size_t)BN * DD];
__device__ __nv_bfloat16 g_cl[(size_t)BN * DD];

// ---------------- ldmatrix / mma helpers -----------------------------------
__device__ __forceinline__ uint32_t smaddr(const void* p) {
    return (uint32_t)__cvta_generic_to_shared(p);
}
__device__ __forceinline__ void ldsm_x4(uint32_t* r, uint32_t a) {
    asm volatile("ldmatrix.sync.aligned.m8n8.x4.shared.b16 {%0,%1,%2,%3}, [%4];"
        : "=r"(r[0]), "=r"(r[1]), "=r"(r[2]), "=r"(r[3]) : "r"(a));
}
__device__ __forceinline__ void ldsm_x4_t(uint32_t* r, uint32_t a) {
    asm volatile("ldmatrix.sync.aligned.m8n8.x4.trans.shared.b16 {%0,%1,%2,%3}, [%4];"
        : "=r"(r[0]), "=r"(r[1]), "=r"(r[2]), "=r"(r[3]) : "r"(a));
}
__device__ __forceinline__ void ldsm_x2(uint32_t* r, uint32_t a) {
    asm volatile("ldmatrix.sync.aligned.m8n8.x2.shared.b16 {%0,%1}, [%2];"
        : "=r"(r[0]), "=r"(r[1]) : "r"(a));
}
__device__ __forceinline__ void ldsm_x2_t(uint32_t* r, uint32_t a) {
    asm volatile("ldmatrix.sync.aligned.m8n8.x2.trans.shared.b16 {%0,%1}, [%2];"
        : "=r"(r[0]), "=r"(r[1]) : "r"(a));
}
__device__ __forceinline__ void mma_bf16(float* d, const uint32_t* a, const uint32_t* b)
{
    asm volatile(
        "mma.sync.aligned.m16n8k16.row.col.f32.bf16.bf16.f32 "
        "{%0,%1,%2,%3},{%4,%5,%6,%7},{%8,%9},{%0,%1,%2,%3};"
        : "+f"(d[0]), "+f"(d[1]), "+f"(d[2]), "+f"(d[3])
        : "r"(a[0]), "r"(a[1]), "r"(a[2]), "r"(a[3]), "r"(b[0]), "r"(b[1]));
}

// ===========================================================================
// Mask dtype detection + expansion (int32 / float32 / uint8 robust)
// ===========================================================================
__global__ void mask_detect_kernel(const unsigned int* __restrict__ mw)
{
    __shared__ int sawF, sawB;
    if (threadIdx.x == 0) { sawF = 0; sawB = 0; }
    __syncthreads();
    for (int i = threadIdx.x; i < 4096; i += 256) {
        unsigned int v = mw[i];
        if (v == 0x3F800000u) atomicOr(&sawF, 1);
        else if (v != 0u && v != 1u) atomicOr(&sawB, 1);
    }
    __syncthreads();
    if (threadIdx.x == 0) g_mask_mode = sawF ? 1 : (sawB ? 2 : 0);
}

__global__ void mask_expand_kernel(const void* __restrict__ m, float* __restrict__ valid)
{
    int i = blockIdx.x * 256 + threadIdx.x;
    if (i >= BN) return;
    int mode = g_mask_mode;
    bool pad;
    if (mode == 0)      pad = ((const int*)m)[i] != 0;
    else if (mode == 1) pad = ((const float*)m)[i] != 0.0f;
    else                pad = ((const unsigned char*)m)[i] != 0;
    valid[i] = pad ? 0.0f : 1.0f;
}

__global__ void convert_split_kernel(const float* __restrict__ src,
                                     __nv_bfloat16* __restrict__ hi,
                                     __nv_bfloat16* __restrict__ lo, int n)
{
    int i = blockIdx.x * 256 + threadIdx.x;
    if (i >= n) return;
    float v = src[i];
    __nv_bfloat16 h = __float2bfloat16(v);
    hi[i] = h;
    lo[i] = __float2bfloat16(v - __bfloat162float(h));
}

__global__ void convert_v_kernel(const float* __restrict__ qkv,
                                 __nv_bfloat16* __restrict__ Vh,
                                 __nv_bfloat16* __restrict__ Vl)
{
    int i = blockIdx.x * 256 + threadIdx.x;
    int row = i >> 10, col = i & 1023;
    float v = qkv[(size_t)row * D3 + 2 * DD + col];
    __nv_bfloat16 h = __float2bfloat16(v);
    Vh[i] = h;
    Vl[i] = __float2bfloat16(v - __bfloat162float(h));
}

// ===========================================================================
// bf16x3 tensor-core GEMM, ldmatrix mainloop (round-8 proven version).
// C = A(MxK)*Bt(NxK)^T + bias. Block 128x128, BK=32, 8 warps (64x32 each).
// ===========================================================================
__global__ __launch_bounds__(256, 2) void gemm_bf16x3_nt(
    const __nv_bfloat16* __restrict__ Ahi, const __nv_bfloat16* __restrict__ Alo,
    const __nv_bfloat16* __restrict__ Bhi, const __nv_bfloat16* __restrict__ Blo,
    const float* __restrict__ bias, float* __restrict__ C,
    int Nd, int Kd)
{
    __shared__ uint32_t As_h[128][20];
    __shared__ uint32_t As_l[128][20];
    __shared__ uint32_t Bs_h[128][20];
    __shared__ uint32_t Bs_l[128][20];

    const int tid  = threadIdx.x;
    const int lane = tid & 31;
    const int w    = tid >> 5;
    const int wm   = (w >> 2) * 64;
    const int wn   = (w & 3) * 32;
    const int q    = lane & 3;
    const int g    = lane >> 2;
    const int jj   = lane >> 3;
    const int rr   = lane & 7;
    const int rowBase = blockIdx.y * 128;
    const int colBase = blockIdx.x * 128;

    float acc[4][4][4];
#pragma unroll
    for (int mt = 0; mt < 4; mt++)
#pragma unroll
        for (int nt = 0; nt < 4; nt++)
#pragma unroll
            for (int e = 0; e < 4; e++) acc[mt][nt][e] = 0.f;

    for (int k0 = 0; k0 < Kd; k0 += 32) {
#pragma unroll
        for (int t = 0; t < 2; t++) {
            int v  = tid + t * 256;
            int r  = v >> 2;
            int ch = v & 3;
            size_t ga = (size_t)(rowBase + r) * Kd + k0 + ch * 8;
            size_t gb = (size_t)(colBase + r) * Kd + k0 + ch * 8;
            *reinterpret_cast<uint4*>(&As_h[r][ch * 4]) = *reinterpret_cast<const uint4*>(Ahi + ga);
            *reinterpret_cast<uint4*>(&As_l[r][ch * 4]) = *reinterpret_cast<const uint4*>(Alo + ga);
            *reinterpret_cast<uint4*>(&Bs_h[r][ch * 4]) = *reinterpret_cast<const uint4*>(Bhi + gb);
            *reinterpret_cast<uint4*>(&Bs_l[r][ch * 4]) = *reinterpret_cast<const uint4*>(Blo + gb);
        }
        __syncthreads();

#pragma unroll
        for (int kko = 0; kko < 32; kko += 16) {
            uint32_t bhf[4][2], blf[4][2], tmp[4];
#pragma unroll
            for (int pp = 0; pp < 2; pp++) {
                int nrow = wn + pp * 16 + (jj >> 1) * 8 + rr;
                int kc = kko + (jj & 1) * 8;
                ldsm_x4(tmp, smaddr(reinterpret_cast<const uint8_t*>(Bs_h) + nrow * 80 + kc * 2));
                bhf[pp*2][0] = tmp[0]; bhf[pp*2][1] = tmp[1];
                bhf[pp*2+1][0] = tmp[2]; bhf[pp*2+1][1] = tmp[3];
                ldsm_x4(tmp, smaddr(reinterpret_cast<const uint8_t*>(Bs_l) + nrow * 80 + kc * 2));
                blf[pp*2][0] = tmp[0]; blf[pp*2][1] = tmp[1];
                blf[pp*2+1][0] = tmp[2]; blf[pp*2+1][1] = tmp[3];
            }
#pragma unroll
            for (int mt = 0; mt < 4; mt++) {
                int arow = wm + mt * 16 + (jj & 1) * 8 + rr;
                int kc = kko + (jj >> 1) * 8;
                uint32_t ah[4], al[4];
                ldsm_x4(ah, smaddr(reinterpret_cast<const uint8_t*>(As_h) + arow * 80 + kc * 2));
                ldsm_x4(al, smaddr(reinterpret_cast<const uint8_t*>(As_l) + arow * 80 + kc * 2));
#pragma unroll
                for (int nt = 0; nt < 4; nt++) {
                    mma_bf16(acc[mt][nt], ah, bhf[nt]);
                    mma_bf16(acc[mt][nt], ah, blf[nt]);
                    mma_bf16(acc[mt][nt], al, bhf[nt]);
                }
            }
        }
        __syncthreads();
    }

#pragma unroll
    for (int mt = 0; mt < 4; mt++) {
        int r0 = rowBase + wm + mt * 16 + g;
#pragma unroll
        for (int nt = 0; nt < 4; nt++) {
            int c = colBase + wn + nt * 8 + q * 2;
            float b0 = bias[c], b1 = bias[c + 1];
            float2* p0 = reinterpret_cast<float2*>(C + (size_t)r0 * Nd + c);
            float2* p1 = reinterpret_cast<float2*>(C + (size_t)(r0 + 8) * Nd + c);
            *p0 = make_float2(acc[mt][nt][0] + b0, acc[mt][nt][1] + b1);
            *p1 = make_float2(acc[mt][nt][2] + b0, acc[mt][nt][3] + b1);
        }
    }
}

// ===========================================================================
// phi_mma: tensor-core phi, STATIC smem (37.5KB), omega streamed in 4 chunks.
// Per block: 64 rows of one (bh, Q|K).
//   proj(64x256) = T(64x64) @ omega[h]^T  via bf16x3 mma,
//   base = -rowmax(proj) - 0.5|t|^2,  out = __expf(proj+base)*post -> hi/lo.
// 8 warps: 4 row-groups (16 rows) x 2 col-groups (32 m per chunk).
// ===========================================================================
#define PHI_AH   0
#define PHI_AL   9216
#define PHI_BH   18432
#define PHI_BL   27648
#define PHI_SQ   36864
#define PHI_MAXS 37120
#define PHI_VAL  37632
#define PHI_SMEM 37888

__global__ __launch_bounds__(256) void phi_mma(
    const float* __restrict__ qkv,
    const __nv_bfloat16* __restrict__ omh, const __nv_bfloat16* __restrict__ oml,
    const float* __restrict__ valid,
    __nv_bfloat16* __restrict__ QfH, __nv_bfloat16* __restrict__ QfL,
    __nv_bfloat16* __restrict__ KfH, __nv_bfloat16* __restrict__ KfL)
{
    __shared__ __align__(16) uint8_t sm[PHI_SMEM];
    float* sqS   = reinterpret_cast<float*>(sm + PHI_SQ);
    float* maxS  = reinterpret_cast<float*>(sm + PHI_MAXS);
    float* valS  = reinterpret_cast<float*>(sm + PHI_VAL);

    const int ntile = blockIdx.x;
    const int bh    = blockIdx.y;
    const int isK   = blockIdx.z;
    const int b = bh >> 4, h = bh & 15;
    const int n0 = ntile * 64;
    const int tid = threadIdx.x;
    const int lane = tid & 31;
    const int w = tid >> 5;
    const int wrow = (w >> 1) * 16;     // 0,16,32,48
    const int cgrp = w & 1;             // col group 0/1 within each 64-m chunk
    const int jj = lane >> 3, rr = lane & 7;
    const int q = lane & 3, g = lane >> 2;

    if (tid < 64) valS[tid] = valid[b * NN + n0 + tid];
    __syncthreads();

    const float* src = qkv + ((size_t)(b * NN + n0)) * D3 + (size_t)isK * DD + h * DKK;

    // stage T as bf16 hi/lo [64 rows][64 k], row stride 144B
    for (int i = tid; i < 64 * 64; i += 256) {
        int r = i >> 6, k = i & 63;
        float v = src[(size_t)r * D3 + k];
        if (!isK) v *= valS[r];
        __nv_bfloat16 hh = __float2bfloat16(v);
        *reinterpret_cast<uint16_t*>(sm + PHI_AH + r * 144 + k * 2) =
            *reinterpret_cast<uint16_t*>(&hh);
        __nv_bfloat16 ll = __float2bfloat16(v - __bfloat162float(hh));
        *reinterpret_cast<uint16_t*>(sm + PHI_AL + r * 144 + k * 2) =
            *reinterpret_cast<uint16_t*>(&ll);
    }
    // sq = 0.5*|t|^2 (deterministic: fixed partial order + pairwise shfl)
    {
        int r = w * 8 + (lane >> 2);
        int part = lane & 3;
        const float* rp = src + (size_t)r * D3;
        float s = 0.f;
        float vm = isK ? 1.f : valS[r];
#pragma unroll
        for (int k = 0; k < 16; k++) {
            float v = rp[part * 16 + k] * vm;
            s += v * v;
        }
        s += __shfl_xor_sync(0xffffffffu, s, 1);
        s += __shfl_xor_sync(0xffffffffu, s, 2);
        if (part == 0) sqS[r] = 0.5f * s;
    }

    float acc[16][4];            // [mchunk*4 + nt][e]
#pragma unroll
    for (int ci = 0; ci < 16; ci++)
#pragma unroll
        for (int e = 0; e < 4; e++) acc[ci][e] = 0.f;

    const uint4* oh4 = reinterpret_cast<const uint4*>(omh + (size_t)h * MM * DKK);
    const uint4* ol4 = reinterpret_cast<const uint4*>(oml + (size_t)h * MM * DKK);

    for (int mchunk = 0; mchunk < 4; mchunk++) {
        __syncthreads();           // prior compute done (also orders T/sq staging)
        // stage omega chunk [64 m][64 k] hi/lo, row stride 144B
        for (int i = tid; i < 512; i += 256) {
            int r = i >> 3, c = i & 7;            // r: 0..63, c: 16B chunk
            int gr = mchunk * 64 + r;
            *reinterpret_cast<uint4*>(sm + PHI_BH + r * 144 + c * 16) = oh4[gr * 8 + c];
            *reinterpret_cast<uint4*>(sm + PHI_BL + r * 144 + c * 16) = ol4[gr * 8 + c];
        }
        __syncthreads();

#pragma unroll
        for (int kko = 0; kko < 64; kko += 16) {
            uint32_t ah[4], al[4];
            {
                int arow = wrow + (jj & 1) * 8 + rr;
                int kc = kko + (jj >> 1) * 8;
                ldsm_x4(ah, smaddr(sm + PHI_AH + arow * 144 + kc * 2));
                ldsm_x4(al, smaddr(sm + PHI_AL + arow * 144 + kc * 2));
            }
#pragma unroll
            for (int pp = 0; pp < 2; pp++) {
                int nrow = cgrp * 32 + pp * 16 + (jj >> 1) * 8 + rr;
                int kc = kko + (jj & 1) * 8;
                uint32_t th[4], tl[4];
                ldsm_x4(th, smaddr(sm + PHI_BH + nrow * 144 + kc * 2));
                ldsm_x4(tl, smaddr(sm + PHI_BL + nrow * 144 + kc * 2));
                uint32_t b0h[2] = { th[0], th[1] }, b1h[2] = { th[2], th[3] };
                uint32_t b0l[2] = { tl[0], tl[1] }, b1l[2] = { tl[2], tl[3] };
                int ci = mchunk * 4 + pp * 2;
                mma_bf16(acc[ci],     ah, b0h);
                mma_bf16(acc[ci],     ah, b0l);
                mma_bf16(acc[ci],     al, b0h);
                mma_bf16(acc[ci + 1], ah, b1h);
                mma_bf16(acc[ci + 1], ah, b1l);
                mma_bf16(acc[ci + 1], al, b1h);
            }
        }
    }

    // row max: thread-local -> shfl over q -> smem combine across col groups
    float m0 = acc[0][0], m8 = acc[0][2];
#pragma unroll
    for (int ci = 0; ci < 16; ci++) {
        m0 = fmaxf(m0, fmaxf(acc[ci][0], acc[ci][1]));
        m8 = fmaxf(m8, fmaxf(acc[ci][2], acc[ci][3]));
    }
    m0 = fmaxf(m0, __shfl_xor_sync(0xffffffffu, m0, 1));
    m0 = fmaxf(m0, __shfl_xor_sync(0xffffffffu, m0, 2));
    m8 = fmaxf(m8, __shfl_xor_sync(0xffffffffu, m8, 1));
    m8 = fmaxf(m8, __shfl_xor_sync(0xffffffffu, m8, 2));
    if (q == 0) {
        maxS[(wrow + g) * 2 + cgrp]     = m0;
        maxS[(wrow + g + 8) * 2 + cgrp] = m8;
    }
    __syncthreads();

    const int r0 = wrow + g, r8 = r0 + 8;
    float base0 = -fmaxf(maxS[r0 * 2], maxS[r0 * 2 + 1]) - sqS[r0];
    float base8 = -fmaxf(maxS[r8 * 2], maxS[r8 * 2 + 1]) - sqS[r8];
    float post0 = isK ? (INV_SQRT_M * valS[r0]) : INV_SQRT_M;
    float post8 = isK ? (INV_SQRT_M * valS[r8]) : INV_SQRT_M;

    size_t off = ((size_t)bh * NN + n0) * MM;
    __nv_bfloat16* dh = (isK ? KfH : QfH) + off;
    __nv_bfloat16* dl = (isK ? KfL : QfL) + off;
#pragma unroll
    for (int ci = 0; ci < 16; ci++) {
        int c = (ci >> 2) * 64 + cgrp * 32 + (ci & 3) * 8 + q * 2;
        float v0 = __expf(acc[ci][0] + base0) * post0;
        float v1 = __expf(acc[ci][1] + base0) * post0;
        float v2 = __expf(acc[ci][2] + base8) * post8;
        float v3 = __expf(acc[ci][3] + base8) * post8;
        __nv_bfloat162 h0, l0, h2, l2;
        h0.x = __float2bfloat16(v0); h0.y = __float2bfloat16(v1);
        l0.x = __float2bfloat16(v0 - __bfloat162float(h0.x));
        l0.y = __float2bfloat16(v1 - __bfloat162float(h0.y));
        h2.x = __float2bfloat16(v2); h2.y = __float2bfloat16(v3);
        l2.x = __float2bfloat16(v2 - __bfloat162float(h2.x));
        l2.y = __float2bfloat16(v3 - __bfloat162float(h2.y));
        *reinterpret_cast<__nv_bfloat162*>(dh + (size_t)r0 * MM + c) = h0;
        *reinterpret_cast<__nv_bfloat162*>(dl + (size_t)r0 * MM + c) = l0;
        *reinterpret_cast<__nv_bfloat162*>(dh + (size_t)r8 * MM + c) = h2;
        *reinterpret_cast<__nv_bfloat162*>(dl + (size_t)r8 * MM + c) = l2;
    }
}

// ===========================================================================
// s_kernel_mma: Spart = Kf^T [V | 1]  (round-8 proven version)
// ===========================================================================
__global__ __launch_bounds__(256) void s_kernel_mma(
    const __nv_bfloat16* __restrict__ KfH, const __nv_bfloat16* __restrict__ KfL,
    const __nv_bfloat16* __restrict__ Vh,  const __nv_bfloat16* __restrict__ Vl,
    float* __restrict__ Spart, float* __restrict__ Kpart)
{
    __shared__ __align__(16) uint8_t KsH[32 * 528];
    __shared__ __align__(16) uint8_t KsL[32 * 528];
    __shared__ __align__(16) uint8_t VsH[32 * 176];
    __shared__ __align__(16) uint8_t VsL[32 * 176];

    const int chunk = blockIdx.x;
    const int bh    = blockIdx.y;
    const int b = bh >> 4, h = bh & 15;
    const int tid = threadIdx.x;
    const int lane = tid & 31;
    const int w = tid >> 5;
    const int wm = (w >> 1) * 64;
    const int dgrp = w & 1;
    const int dbase = dgrp ? 32 : 0;
    const int NT = dgrp ? 5 : 4;

    float acc[4][5][4];
#pragma unroll
    for (int mt = 0; mt < 4; mt++)
#pragma unroll
        for (int nt = 0; nt < 5; nt++)
#pragma unroll
            for (int e = 0; e < 4; e++) acc[mt][nt][e] = 0.f;

    const uint4 ones_hi = make_uint4(0x00003F80u, 0u, 0u, 0u);
    const uint4 zero4   = make_uint4(0u, 0u, 0u, 0u);

    for (int it = 0; it < NN / NCHUNK / 32; it++) {
        const int nbase = chunk * (NN / NCHUNK) + it * 32;
        __syncthreads();
        for (int i = tid; i < 1024; i += 256) {
            int nn = i >> 5, mc = i & 31;
            size_t src = ((size_t)bh * NN + nbase + nn) * MM + mc * 8;
            *reinterpret_cast<uint4*>(KsH + nn * 528 + mc * 16) =
                *reinterpret_cast<const uint4*>(KfH + src);
            *reinterpret_cast<uint4*>(KsL + nn * 528 + mc * 16) =
                *reinterpret_cast<const uint4*>(KfL + src);
        }
        for (int i = tid; i < 288; i += 256) {
            int nn = i / 9, dc = i % 9;
            if (dc < 8) {
                size_t src = ((size_t)(b * NN) + nbase + nn) * 1024 + h * 64 + dc * 8;
                *reinterpret_cast<uint4*>(VsH + nn * 176 + dc * 16) =
                    *reinterpret_cast<const uint4*>(Vh + src);
                *reinterpret_cast<uint4*>(VsL + nn * 176 + dc * 16) =
                    *reinterpret_cast<const uint4*>(Vl + src);
            } else {
                *reinterpret_cast<uint4*>(VsH + nn * 176 + 128) = ones_hi;
                *reinterpret_cast<uint4*>(VsL + nn * 176 + 128) = zero4;
            }
        }
        __syncthreads();

#pragma unroll
        for (int kko = 0; kko < 32; kko += 16) {
            const int jj = lane >> 3, rr = lane & 7;
            const int krow = kko + rr + (jj >> 1) * 8;
            uint32_t ah[4][4], al[4][4];
#pragma unroll
            for (int mt = 0; mt < 4; mt++) {
                int mcol = wm + mt * 16 + (jj & 1) * 8;
                ldsm_x4_t(ah[mt], smaddr(KsH + krow * 528 + mcol * 2));
                ldsm_x4_t(al[mt], smaddr(KsL + krow * 528 + mcol * 2));
            }
            uint32_t bhf[5][2], blf[5][2], tmp[4];
#pragma unroll
            for (int pp = 0; pp < 2; pp++) {
                int dcol  = dbase + pp * 16 + ((lane >> 4) ? 8 : 0);
                int krowb = kko + rr + ((jj & 1) ? 8 : 0);
                ldsm_x4_t(tmp, smaddr(VsH + krowb * 176 + dcol * 2));
                bhf[pp*2][0] = tmp[0]; bhf[pp*2][1] = tmp[1];
                bhf[pp*2+1][0] = tmp[2]; bhf[pp*2+1][1] = tmp[3];
                ldsm_x4_t(tmp, smaddr(VsL + krowb * 176 + dcol * 2));
                blf[pp*2][0] = tmp[0]; blf[pp*2][1] = tmp[1];
                blf[pp*2+1][0] = tmp[2]; blf[pp*2+1][1] = tmp[3];
            }
            if (dgrp) {
                int krow2 = kko + (lane & 7) + ((lane & 8) ? 8 : 0);
                ldsm_x2_t(tmp, smaddr(VsH + krow2 * 176 + 64 * 2));
                bhf[4][0] = tmp[0]; bhf[4][1] = tmp[1];
                ldsm_x2_t(tmp, smaddr(VsL + krow2 * 176 + 64 * 2));
                blf[4][0] = tmp[0]; blf[4][1] = tmp[1];
            }
#pragma unroll
            for (int mt = 0; mt < 4; mt++)
                for (int nt = 0; nt < NT; nt++) {
                    mma_bf16(acc[mt][nt], ah[mt], bhf[nt]);
                    mma_bf16(acc[mt][nt], ah[mt], blf[nt]);
                    mma_bf16(acc[mt][nt], al[mt], bhf[nt]);
                }
        }
    }

    float* Sp = Spart + ((size_t)chunk * BH + bh) * (MM * 64);
    float* Kp = Kpart + ((size_t)chunk * BH + bh) * MM;
    const int g = lane >> 2, q = lane & 3;
#pragma unroll
    for (int mt = 0; mt < 4; mt++) {
        int m = wm + mt * 16 + g;
        for (int nt = 0; nt < NT; nt++) {
            int d = dbase + nt * 8 + q * 2;
            if (d < 64) {
                *reinterpret_cast<float2*>(Sp + m * 64 + d) =
                    make_float2(acc[mt][nt][0], acc[mt][nt][1]);
                *reinterpret_cast<float2*>(Sp + (m + 8) * 64 + d) =
                    make_float2(acc[mt][nt][2], acc[mt][nt][3]);
            } else if (d == 64) {
                Kp[m]     = acc[mt][nt][0];
                Kp[m + 8] = acc[mt][nt][2];
            }
        }
    }
}

__global__ __launch_bounds__(256) void reduce2(
    const float* __restrict__ Spart, const float* __restrict__ Kpart,
    __nv_bfloat16* __restrict__ StH, __nv_bfloat16* __restrict__ StL)
{
    int i = blockIdx.x * 256 + threadIdx.x;
    if (i >= BH * MM * 72) return;
    int bh = i / (MM * 72);
    int r  = i % (MM * 72);
    int m  = r / 72;
    int dd = r % 72;
    float s = 0.f;
    if (dd < 64) {
#pragma unroll
        for (int c = 0; c < NCHUNK; c++)
            s += Spart[((size_t)c * BH + bh) * (MM * 64) + m * 64 + dd];
    } else if (dd == 64) {
#pragma unroll
        for (int c = 0; c < NCHUNK; c++)
            s += Kpart[((size_t)c * BH + bh) * MM + m];
    }
    __nv_bfloat16 hh = __float2bfloat16(s);
    size_t o = ((size_t)bh * 72 + dd) * MM + m;
    StH[o] = hh;
    StL[o] = __float2bfloat16(s - __bfloat162float(hh));
}

// ===========================================================================
// ctx_kernel_mma: ctx = (Qf @ [S|Ksum]) / den * valid  (round-8 proven)
// ===========================================================================
__global__ __launch_bounds__(256) void ctx_kernel_mma(
    const __nv_bfloat16* __restrict__ QfH, const __nv_bfloat16* __restrict__ QfL,
    const __nv_bfloat16* __restrict__ StH, const __nv_bfloat16* __restrict__ StL,
    const float* __restrict__ valid,
    __nv_bfloat16* __restrict__ ch, __nv_bfloat16* __restrict__ cl)
{
    __shared__ __align__(16) uint8_t QsH[128 * 80];
    __shared__ __align__(16) uint8_t QsL[128 * 80];
    __shared__ __align__(16) uint8_t SsH[72 * 80];
    __shared__ __align__(16) uint8_t SsL[72 * 80];
    __shared__ float denS[128];
    __shared__ float validS[128];

    const int bh = blockIdx.y;
    const int b = bh >> 4, h = bh & 15;
    const int n0 = blockIdx.x * 128;
    const int tid = threadIdx.x;
    const int lane = tid & 31;
    const int w = tid >> 5;
    const int wnb = (w >> 1) * 32;
    const int dgrp = w & 1;
    const int dbase = dgrp ? 32 : 0;
    const int NT = dgrp ? 5 : 4;

    if (tid < 128) validS[tid] = valid[b * NN + n0 + tid];

    float acc[2][5][4];
#pragma unroll
    for (int mt = 0; mt < 2; mt++)
#pragma unroll
        for (int nt = 0; nt < 5; nt++)
#pragma unroll
            for (int e = 0; e < 4; e++) acc[mt][nt][e] = 0.f;

    for (int m0 = 0; m0 < 256; m0 += 32) {
        __syncthreads();
        for (int i = tid; i < 512; i += 256) {
            int nn = i >> 2, mc = i & 3;
            size_t src = ((size_t)bh * NN + n0 + nn) * MM + m0 + mc * 8;
            *reinterpret_cast<uint4*>(QsH + nn * 80 + mc * 16) =
                *reinterpret_cast<const uint4*>(QfH + src);
            *reinterpret_cast<uint4*>(QsL + nn * 80 + mc * 16) =
                *reinterpret_cast<const uint4*>(QfL + src);
        }
        for (int i = tid; i < 288; i += 256) {
            int dd = i >> 2, mc = i & 3;
            size_t src = ((size_t)bh * 72 + dd) * MM + m0 + mc * 8;
            *reinterpret_cast<uint4*>(SsH + dd * 80 + mc * 16) =
                *reinterpret_cast<const uint4*>(StH + src);
            *reinterpret_cast<uint4*>(SsL + dd * 80 + mc * 16) =
                *reinterpret_cast<const uint4*>(StL + src);
        }
        __syncthreads();

#pragma unroll
        for (int kko = 0; kko < 32; kko += 16) {
            const int jj = lane >> 3, rr = lane & 7;
            uint32_t ah[2][4], al[2][4];
#pragma unroll
            for (int mt = 0; mt < 2; mt++) {
                int nrow = wnb + mt * 16 + (jj & 1) * 8 + rr;
                int kc = kko + (jj >> 1) * 8;
                ldsm_x4(ah[mt], smaddr(QsH + nrow * 80 + kc * 2));
                ldsm_x4(al[mt], smaddr(QsL + nrow * 80 + kc * 2));
            }
            uint32_t bhf[5][2], blf[5][2], tmp[4];
#pragma unroll
            for (int pp = 0; pp < 2; pp++) {
                int drow = dbase + pp * 16 + (jj >> 1) * 8 + rr;
                int kc = kko + (jj & 1) * 8;
                ldsm_x4(tmp, smaddr(SsH + drow * 80 + kc * 2));
                bhf[pp*2][0] = tmp[0]; bhf[pp*2][1] = tmp[1];
                bhf[pp*2+1][0] = tmp[2]; bhf[pp*2+1][1] = tmp[3];
                ldsm_x4(tmp, smaddr(SsL + drow * 80 + kc * 2));
                blf[pp*2][0] = tmp[0]; blf[pp*2][1] = tmp[1];
                blf[pp*2+1][0] = tmp[2]; blf[pp*2+1][1] = tmp[3];
            }
            if (dgrp) {
                int drow = 64 + (lane & 7);
                int kc = kko + ((lane & 8) ? 8 : 0);
                ldsm_x2(tmp, smaddr(SsH + drow * 80 + kc * 2));
                bhf[4][0] = tmp[0]; bhf[4][1] = tmp[1];
                ldsm_x2(tmp, smaddr(SsL + drow * 80 + kc * 2));
                blf[4][0] = tmp[0]; blf[4][1] = tmp[1];
            }
#pragma unroll
            for (int mt = 0; mt < 2; mt++)
                for (int nt = 0; nt < NT; nt++) {
                    mma_bf16(acc[mt][nt], ah[mt], bhf[nt]);
                    mma_bf16(acc[mt][nt], ah[mt], blf[nt]);
                    mma_bf16(acc[mt][nt], al[mt], bhf[nt]);
                }
        }
    }

    const int g = lane >> 2, q = lane & 3;
    if (dgrp && q == 0) {
#pragma unroll
        for (int mt = 0; mt < 2; mt++) {
            int n = wnb + mt * 16 + g;
            denS[n]     = acc[mt][4][0];
            denS[n + 8] = acc[mt][4][2];
        }
    }
    __syncthreads();

#pragma unroll
    for (int mt = 0; mt < 2; mt++) {
        int n = wnb + mt * 16 + g;
        float sc0 = validS[n]     / (denS[n]     + EPS_DENOM);
        float sc2 = validS[n + 8] / (denS[n + 8] + EPS_DENOM);
        size_t r0 = ((size_t)(b * NN) + n0 + n) * 1024 + h * 64;
        size_t r2 = r0 + 8 * 1024;
#pragma unroll
        for (int nt = 0; nt < 4; nt++) {
            int d = dbase + nt * 8 + q * 2;
            float v0 = acc[mt][nt][0] * sc0, v1 = acc[mt][nt][1] * sc0;
            float v2 = acc[mt][nt][2] * sc2, v3 = acc[mt][nt][3] * sc2;
            __nv_bfloat162 hh0, ll0, hh2, ll2;
            hh0.x = __float2bfloat16(v0); hh0.y = __float2bfloat16(v1);
            ll0.x = __float2bfloat16(v0 - __bfloat162float(hh0.x));
            ll0.y = __float2bfloat16(v1 - __bfloat162float(hh0.y));
            hh2.x = __float2bfloat16(v2); hh2.y = __float2bfloat16(v3);
            ll2.x = __float2bfloat16(v2 - __bfloat162float(hh2.x));
            ll2.y = __float2bfloat16(v3 - __bfloat162float(hh2.y));
            *reinterpret_cast<__nv_bfloat162*>(ch + r0 + d) = hh0;
            *reinterpret_cast<__nv_bfloat162*>(cl + r0 + d) = ll0;
            *reinterpret_cast<__nv_bfloat162*>(ch + r2 + d) = hh2;
            *reinterpret_cast<__nv_bfloat162*>(cl + r2 + d) = ll2;
        }
    }
}

// ===========================================================================
extern "C" void kernel_launch(void* const* d_in, const int* in_sizes, int n_in,
                              void* d_out, int out_size)
{
    const float* x     = (const float*)d_in[0];
    const float* Wqkv  = (const float*)d_in[1];
    const float* bqkv  = (const float*)d_in[2];
    const float* Wout  = (const float*)d_in[3];
    const float* bout  = (const float*)d_in[4];
    const float* omega = (const float*)d_in[5];
    const void*  maskp = d_in[6];
    float* out = (float*)d_out;

    float *qkv, *Spart, *Kpart, *valid;
    __nv_bfloat16 *QfH, *QfL, *KfH, *KfL, *StH, *StL;
    __nv_bfloat16 *xh, *xl, *Wqh, *Wql, *Woh, *Wol, *omh, *oml, *Vh, *Vl, *ch, *cl;
    cudaGetSymbolAddress((void**)&qkv,   g_qkv);
    cudaGetSymbolAddress((void**)&QfH,   g_QfH);
    cudaGetSymbolAddress((void**)&QfL,   g_QfL);
    cudaGetSymbolAddress((void**)&KfH,   g_KfH);
    cudaGetSymbolAddress((void**)&KfL,   g_KfL);
    cudaGetSymbolAddress((void**)&Spart, g_Spart);
    cudaGetSymbolAddress((void**)&Kpart, g_Kpart);
    cudaGetSymbolAddress((void**)&StH,   g_StH);
    cudaGetSymbolAddress((void**)&StL,   g_StL);
    cudaGetSymbolAddress((void**)&valid, g_valid);
    cudaGetSymbolAddress((void**)&xh,  g_xh);
    cudaGetSymbolAddress((void**)&xl,  g_xl);
    cudaGetSymbolAddress((void**)&Wqh, g_Wqh);
    cudaGetSymbolAddress((void**)&Wql, g_Wql);
    cudaGetSymbolAddress((void**)&Woh, g_Woh);
    cudaGetSymbolAddress((void**)&Wol, g_Wol);
    cudaGetSymbolAddress((void**)&omh, g_omh);
    cudaGetSymbolAddress((void**)&oml, g_oml);
    cudaGetSymbolAddress((void**)&Vh,  g_Vh);
    cudaGetSymbolAddress((void**)&Vl,  g_Vl);
    cudaGetSymbolAddress((void**)&ch,  g_ch);
    cudaGetSymbolAddress((void**)&cl,  g_cl);

    // 0) mask + operand splits
    mask_detect_kernel<<<1, 256>>>((const unsigned int*)maskp);
    mask_expand_kernel<<<BN / 256, 256>>>(maskp, valid);
    convert_split_kernel<<<(BN * DD) / 256, 256>>>(x, xh, xl, BN * DD);
    convert_split_kernel<<<(D3 * DD) / 256, 256>>>(Wqkv, Wqh, Wql, D3 * DD);
    convert_split_kernel<<<(DD * DD) / 256, 256>>>(Wout, Woh, Wol, DD * DD);
    convert_split_kernel<<<(HH * MM * DKK) / 256, 256>>>(omega, omh, oml, HH * MM * DKK);

    // 1) qkv = x @ Wqkv^T + bqkv   (mma.sync bf16x3, ldmatrix)
    gemm_bf16x3_nt<<<dim3(D3 / 128, BN / 128), 256>>>(xh, xl, Wqh, Wql, bqkv, qkv, D3, DD);

    // 1b) split V part of qkv to bf16 hi/lo
    convert_v_kernel<<<(BN * DD) / 256, 256>>>(qkv, Vh, Vl);

    // 2) phi on tensor cores (static smem) -> Qf/Kf bf16 hi/lo
    phi_mma<<<dim3(NN / 64, BH, 2), 256>>>(
        qkv, omh, oml, valid, QfH, QfL, KfH, KfL);

    // 3) S = Kf^T [V | 1]  (split-K + deterministic reduce)
    s_kernel_mma<<<dim3(NCHUNK, BH), 256>>>(KfH, KfL, Vh, Vl, Spart, Kpart);
    reduce2<<<(BH * MM * 72 + 255) / 256, 256>>>(Spart, Kpart, StH, StL);

    // 4) ctx = (Qf @ [S | Ksum]) scaled -> bf16 hi/lo
    ctx_kernel_mma<<<dim3(NN / 128, BH), 256>>>(QfH, QfL, StH, StL, valid, ch, cl);

    // 5) out = ctx @ Wout^T + bout (mma.sync bf16x3, ldmatrix)
    gemm_bf16x3_nt<<<dim3(DD / 128, BN / 128), 256>>>(ch, cl, Woh, Wol, bout, out, DD, DD);
}